// round 13
// baseline (speedup 1.0000x reference)
#include <cuda_runtime.h>
#include <cuda_fp16.h>
#include <cstdint>

#define NG    4
#define NH    12
#define BHD   48
#define NNODE 1024
#define EDIM  768
#define HD    64
#define QSCALE 0.125f
#define LOG2E  1.4426950408889634f
#define MROWS 4096

// ---------------- scratch (no cudaMalloc allowed) ----------------
__device__ __half g_qxh[MROWS * EDIM];       // query rounded fp16
__device__ __half g_wih[3 * EDIM * EDIM];    // W_in rounded
__device__ __half g_woh[EDIM * EDIM];        // W_out rounded
__device__ __half g_qh[BHD * NNODE * HD];    // q rounded (scaled by QSCALE*LOG2E)
__device__ __half g_kh[BHD * NNODE * HD];    // k rounded
__device__ __half g_vh[BHD * NNODE * HD];    // v rounded
__device__ __half g_ah[MROWS * EDIM];        // attn out rounded
__device__ int    g_mask_kind;

// ---------------- helpers ----------------
__device__ __forceinline__ uint32_t smem_u32(const void* p) {
    return (uint32_t)__cvta_generic_to_shared(p);
}
__device__ __forceinline__ void cp16(uint32_t dst, const void* src) {
    asm volatile("cp.async.cg.shared.global [%0],[%1],16;\n" :: "r"(dst), "l"(src) : "memory");
}
__device__ __forceinline__ void cpcommit() {
    asm volatile("cp.async.commit_group;\n" ::: "memory");
}
template<int N> __device__ __forceinline__ void cpwait() {
    asm volatile("cp.async.wait_group %0;\n" :: "n"(N) : "memory");
}
__device__ __forceinline__ void ldmx4(uint32_t& r0, uint32_t& r1, uint32_t& r2, uint32_t& r3, uint32_t a) {
    asm volatile("ldmatrix.sync.aligned.m8n8.x4.shared.b16 {%0,%1,%2,%3},[%4];\n"
                 : "=r"(r0), "=r"(r1), "=r"(r2), "=r"(r3) : "r"(a));
}
__device__ __forceinline__ void ldmx4t(uint32_t& r0, uint32_t& r1, uint32_t& r2, uint32_t& r3, uint32_t a) {
    asm volatile("ldmatrix.sync.aligned.m8n8.x4.trans.shared.b16 {%0,%1,%2,%3},[%4];\n"
                 : "=r"(r0), "=r"(r1), "=r"(r2), "=r"(r3) : "r"(a));
}
__device__ __forceinline__ void mma16816(float* c, const uint32_t* a, uint32_t b0, uint32_t b1) {
    asm volatile("mma.sync.aligned.m16n8k16.row.col.f32.f16.f16.f32 "
                 "{%0,%1,%2,%3},{%4,%5,%6,%7},{%8,%9},{%0,%1,%2,%3};\n"
                 : "+f"(c[0]), "+f"(c[1]), "+f"(c[2]), "+f"(c[3])
                 : "r"(a[0]), "r"(a[1]), "r"(a[2]), "r"(a[3]), "r"(b0), "r"(b1));
}
__device__ __forceinline__ uint32_t pack_half2(float x, float y) {
    __half2 h = __floats2half2_rn(x, y);
    return *reinterpret_cast<uint32_t*>(&h);
}
__device__ __forceinline__ float ex2f(float x) {
    float y; asm("ex2.approx.ftz.f32 %0,%1;" : "=f"(y) : "f"(x)); return y;
}
__device__ __forceinline__ uint32_t ex2h2(uint32_t x) {
    uint32_t y; asm("ex2.approx.f16x2 %0,%1;" : "=r"(y) : "r"(x)); return y;
}

// ---------------- fused prep: round q/W_in/W_out; last block also probes mask
#define NQ4  (MROWS * EDIM / 4)
#define NWI4 (3 * EDIM * EDIM / 4)
#define NWO4 (EDIM * EDIM / 4)
#define PREP_BLOCKS ((NQ4 + NWI4 + NWO4 + 255) / 256)
__global__ void prep_kernel(const float4* __restrict__ q,
                            const float4* __restrict__ wi,
                            const float4* __restrict__ wo,
                            const uint8_t* __restrict__ mask) {
    int i = blockIdx.x * blockDim.x + threadIdx.x;
    if (i < NQ4) {
        float4 f = q[i];
        ((uint2*)g_qxh)[i] = make_uint2(pack_half2(f.x, f.y), pack_half2(f.z, f.w));
    } else if (i < NQ4 + NWI4) {
        int j = i - NQ4;
        float4 f = wi[j];
        ((uint2*)g_wih)[j] = make_uint2(pack_half2(f.x, f.y), pack_half2(f.z, f.w));
    } else if (i < NQ4 + NWI4 + NWO4) {
        int j = i - NQ4 - NWI4;
        float4 f = wo[j];
        ((uint2*)g_woh)[j] = make_uint2(pack_half2(f.x, f.y), pack_half2(f.z, f.w));
    }
    if (blockIdx.x == gridDim.x - 1) {
        __shared__ int or_b0, or_b123;
        if (threadIdx.x == 0) { or_b0 = 0; or_b123 = 0; }
        __syncthreads();
        int a0 = 0, a123 = 0;
        for (int w = threadIdx.x; w < 1024; w += blockDim.x) {
            a0   |= mask[4 * w];
            a123 |= mask[4 * w + 1] | mask[4 * w + 2] | mask[4 * w + 3];
        }
        if (a0)   atomicOr(&or_b0, 1);
        if (a123) atomicOr(&or_b123, 1);
        __syncthreads();
        if (threadIdx.x == 0) {
            if (or_b0 == 0)        g_mask_kind = 2;
            else if (or_b123 == 0) g_mask_kind = 1;
            else                   g_mask_kind = 0;
        }
    }
}

// ============================================================================
// qkv GEMM: BM=128, BN=128, BK=64, 256 threads (8 warps 2x4), warp 64x32.
// 3-stage cp.async ring, one barrier per k-iter (12 iters).
// ============================================================================
#define GSTG 32768   // A 16384 + B 16384

__device__ __forceinline__ void gemm_load_stage(
    uint32_t sbase, const __half* A, const __half* B,
    int m0, int n0, int k0, int tid)
{
    uint32_t aH = sbase, bH = sbase + 16384;
#pragma unroll
    for (int it = 0; it < 4; it++) {
        int s = tid + it * 256;
        int row = s >> 3, ch = s & 7;
        uint32_t off = (uint32_t)(row * 128 + ((ch ^ (row & 7)) * 16));
        cp16(aH + off, A + (size_t)(m0 + row) * EDIM + k0 + ch * 8);
        cp16(bH + off, B + (size_t)(n0 + row) * EDIM + k0 + ch * 8);
    }
}

__device__ __forceinline__ void gemm_compute_stage(
    uint32_t sbase, int lane, int wm, int wn, float acc[4][4][4])
{
    uint32_t aH = sbase, bH = sbase + 16384;
#pragma unroll
    for (int kc = 0; kc < 4; kc++) {
        uint32_t ah[4][4], bh[2][4];
#pragma unroll
        for (int mt = 0; mt < 4; mt++) {
            int row = wm + mt * 16 + (lane & 15);
            int ch = (kc * 2 + (lane >> 4)) ^ (row & 7);
            ldmx4(ah[mt][0], ah[mt][1], ah[mt][2], ah[mt][3], aH + row * 128 + ch * 16);
        }
#pragma unroll
        for (int pr = 0; pr < 2; pr++) {
            int row = wn + pr * 16 + ((lane >> 4) << 3) + (lane & 7);
            int ch = (kc * 2 + ((lane >> 3) & 1)) ^ (row & 7);
            ldmx4(bh[pr][0], bh[pr][1], bh[pr][2], bh[pr][3], bH + row * 128 + ch * 16);
        }
#pragma unroll
        for (int mt = 0; mt < 4; mt++)
#pragma unroll
            for (int nt = 0; nt < 4; nt++)
                mma16816(acc[mt][nt], ah[mt],
                         bh[nt >> 1][(nt & 1) * 2], bh[nt >> 1][(nt & 1) * 2 + 1]);
    }
}

__global__ __launch_bounds__(256, 2) void qkv_gemm_kernel(const float* __restrict__ bias)
{
    extern __shared__ __align__(16) char dynsm[];
    const int tid = threadIdx.x, lane = tid & 31, warp = tid >> 5;
    const int wm = (warp >> 2) * 64, wn = (warp & 3) * 32;
    const int m0 = blockIdx.x * 128, n0 = blockIdx.y * 128;
    const uint32_t sb = smem_u32(dynsm);
    gemm_load_stage(sb,        g_qxh, g_wih, m0, n0, 0,  tid);
    cpcommit();
    gemm_load_stage(sb + GSTG, g_qxh, g_wih, m0, n0, 64, tid);
    cpcommit();
    float acc[4][4][4] = {};
    for (int kt = 0; kt < 12; kt++) {
        cpwait<1>();
        __syncthreads();
        gemm_compute_stage(sb + (kt % 3) * GSTG, lane, wm, wn, acc);
        if (kt + 2 < 12)
            gemm_load_stage(sb + ((kt + 2) % 3) * GSTG, g_qxh, g_wih,
                            m0, n0, (kt + 2) * 64, tid);
        cpcommit();
    }

    const int g = lane >> 2, c = lane & 3;
    const int sec = n0 / EDIM;
    const int colbase = n0 - sec * EDIM;
    const float sc = (sec == 0) ? QSCALE * LOG2E : 1.0f;
    __half* dst = (sec == 0) ? g_qh : (sec == 1 ? g_kh : g_vh);
#pragma unroll
    for (int mt = 0; mt < 4; mt++)
#pragma unroll
        for (int nt = 0; nt < 4; nt++) {
            int dloc = wn + nt * 8 + 2 * c;
            int e = colbase + dloc;
            int hh = e >> 6, d = e & 63;
            float bv0 = bias[n0 + dloc], bv1 = bias[n0 + dloc + 1];
#pragma unroll
            for (int rr = 0; rr < 2; rr++) {
                int row = m0 + wm + mt * 16 + g + rr * 8;
                int node = row >> 2, bg = row & 3;
                float v0 = (acc[mt][nt][rr * 2 + 0] + bv0) * sc;
                float v1 = (acc[mt][nt][rr * 2 + 1] + bv1) * sc;
                size_t idx = (((size_t)(bg * NH + hh) * NNODE + node) * HD + d);
                *(uint32_t*)&dst[idx] = pack_half2(v0, v1);
            }
        }
}

// ============================================================================
// out GEMM: BM=64, BN=128, BK=64, 256 threads (8 warps 2x4), warp 32x32.
// 4-stage cp.async ring (96 KB, 2 CTA/SM) for deeper prefetch.
// ============================================================================
#define OSTG 24576   // A 8192 + B 16384

__device__ __forceinline__ void ogemm_load_stage(
    uint32_t sbase, int m0, int n0, int k0, int tid)
{
    uint32_t aH = sbase, bH = sbase + 8192;
#pragma unroll
    for (int it = 0; it < 2; it++) {
        int s = tid + it * 256;
        int row = s >> 3, ch = s & 7;
        uint32_t off = (uint32_t)(row * 128 + ((ch ^ (row & 7)) * 16));
        cp16(aH + off, g_ah + (size_t)(m0 + row) * EDIM + k0 + ch * 8);
    }
#pragma unroll
    for (int it = 0; it < 4; it++) {
        int s = tid + it * 256;
        int row = s >> 3, ch = s & 7;
        uint32_t off = (uint32_t)(row * 128 + ((ch ^ (row & 7)) * 16));
        cp16(bH + off, g_woh + (size_t)(n0 + row) * EDIM + k0 + ch * 8);
    }
}

__device__ __forceinline__ void ogemm_compute_stage(
    uint32_t sbase, int lane, int wm, int wn, float acc[2][4][4])
{
    uint32_t aH = sbase, bH = sbase + 8192;
#pragma unroll
    for (int kc = 0; kc < 4; kc++) {
        uint32_t ah[2][4], bh[2][4];
#pragma unroll
        for (int mt = 0; mt < 2; mt++) {
            int row = wm + mt * 16 + (lane & 15);
            int ch = (kc * 2 + (lane >> 4)) ^ (row & 7);
            ldmx4(ah[mt][0], ah[mt][1], ah[mt][2], ah[mt][3], aH + row * 128 + ch * 16);
        }
#pragma unroll
        for (int pr = 0; pr < 2; pr++) {
            int row = wn + pr * 16 + ((lane >> 4) << 3) + (lane & 7);
            int ch = (kc * 2 + ((lane >> 3) & 1)) ^ (row & 7);
            ldmx4(bh[pr][0], bh[pr][1], bh[pr][2], bh[pr][3], bH + row * 128 + ch * 16);
        }
#pragma unroll
        for (int mt = 0; mt < 2; mt++)
#pragma unroll
            for (int nt = 0; nt < 4; nt++)
                mma16816(acc[mt][nt], ah[mt],
                         bh[nt >> 1][(nt & 1) * 2], bh[nt >> 1][(nt & 1) * 2 + 1]);
    }
}

__global__ __launch_bounds__(256, 2) void out_gemm_kernel(
    const float* __restrict__ bias, const void* __restrict__ maskp,
    float* __restrict__ out)
{
    extern __shared__ __align__(16) char dynsm[];
    const int tid = threadIdx.x, lane = tid & 31, warp = tid >> 5;
    const int wm = (warp >> 2) * 32, wn = (warp & 3) * 32;
    const int m0 = blockIdx.x * 64, n0 = blockIdx.y * 128;
    const uint32_t sb = smem_u32(dynsm);
    ogemm_load_stage(sb,            m0, n0, 0,   tid); cpcommit();
    ogemm_load_stage(sb + OSTG,     m0, n0, 64,  tid); cpcommit();
    ogemm_load_stage(sb + 2 * OSTG, m0, n0, 128, tid); cpcommit();
    float acc[2][4][4] = {};
    for (int kt = 0; kt < 12; kt++) {
        cpwait<2>();
        __syncthreads();
        ogemm_compute_stage(sb + (kt % 4) * OSTG, lane, wm, wn, acc);
        if (kt + 3 < 12)
            ogemm_load_stage(sb + ((kt + 3) % 4) * OSTG, m0, n0, (kt + 3) * 64, tid);
        cpcommit();
    }

    const int g = lane >> 2, c = lane & 3;
    const int mkind = g_mask_kind;
#pragma unroll
    for (int mt = 0; mt < 2; mt++)
#pragma unroll
        for (int rr = 0; rr < 2; rr++) {
            int row = m0 + wm + mt * 16 + g + rr * 8;
            int node = row >> 2, bg = row & 3;
            int midx = bg * NNODE + node;
            bool keep;
            if (mkind == 1)      keep = ((const int*)maskp)[midx] != 0;
            else if (mkind == 2) keep = ((const float*)maskp)[midx] != 0.0f;
            else                 keep = ((const uint8_t*)maskp)[midx] != 0;
#pragma unroll
            for (int nt = 0; nt < 4; nt++) {
                int col = n0 + wn + nt * 8 + 2 * c;
                float v0 = keep ? (acc[mt][nt][rr * 2 + 0] + bias[col])     : 0.0f;
                float v1 = keep ? (acc[mt][nt][rr * 2 + 1] + bias[col + 1]) : 0.0f;
                *(float2*)&out[(size_t)row * EDIM + col] = make_float2(v0, v1);
            }
        }
}

// ============================================================================
// Kernel 2: flash attention with LAZY MAX (one-stage-delayed shift).
// CTA = 128 q-rows x 1 head, 8 warps, 2 CTA/SM. 16 key-stages of 64 keys;
// 2-stage cp.async ring (KV + fp32 bias in XOR-swizzled smem).
// P = ex2(S - m_old); max reduction + rescale run AFTER PV (off critical path).
// ============================================================================
#define ASTG 49152    // Kh 8192 + Vh 8192 + bias 32768
#define ONES2 0x3C003C00u

__device__ __forceinline__ void attn_load_stage(
    uint32_t sbase, size_t kvbase, const float* bb, int m0, int n0, int tid)
{
    uint32_t kH = sbase, vH = sbase + 8192, bS = sbase + 16384;
#pragma unroll
    for (int it = 0; it < 2; it++) {
        int s = tid + it * 256;
        int row = s >> 3, ch = s & 7;
        uint32_t off = (uint32_t)(row * 128 + ((ch ^ (row & 7)) * 16));
        size_t gi = kvbase + (size_t)(m0 + row) * HD + ch * 8;
        cp16(kH + off, g_kh + gi);
        cp16(vH + off, g_vh + gi);
    }
#pragma unroll
    for (int it = 0; it < 8; it++) {
        int s = tid + it * 256;
        int row = s >> 4, ch = s & 15;
        cp16(bS + (uint32_t)(row * 256 + ((ch ^ (row & 15)) << 4)),
             bb + (size_t)(n0 + row) * NNODE + m0 + ch * 4);
    }
}

__global__ __launch_bounds__(256, 2) void attn_kernel(const float* __restrict__ bias)
{
    extern __shared__ __align__(16) char dynsm[];
    const int tid = threadIdx.x, lane = tid & 31, warp = tid >> 5;
    const int bh = blockIdx.y, n0 = blockIdx.x * 128;
    const size_t base = (size_t)bh * NNODE * HD;
    const float* bb = bias + ((size_t)bh << 20);

    const uint32_t qH = smem_u32(dynsm);
    const uint32_t st0 = qH + 16384;

    // prologue: Q (own group), then stages 0,1
#pragma unroll
    for (int it = 0; it < 4; it++) {
        int s = tid + it * 256;
        int row = s >> 3, ch = s & 7;
        uint32_t off = (uint32_t)(row * 128 + ((ch ^ (row & 7)) * 16));
        cp16(qH + off, g_qh + base + (size_t)(n0 + row) * HD + ch * 8);
    }
    cpcommit();
    attn_load_stage(st0, base, bb, 0, n0, tid);
    cpcommit();
    attn_load_stage(st0 + ASTG, base, bb, 64, n0, tid);
    cpcommit();

    cpwait<2>();
    __syncthreads();
    uint32_t qh[4][4];
#pragma unroll
    for (int kc = 0; kc < 4; kc++) {
        int row = warp * 16 + (lane & 15);
        int ch = (kc * 2 + (lane >> 4)) ^ (row & 7);
        ldmx4(qh[kc][0], qh[kc][1], qh[kc][2], qh[kc][3], qH + row * 128 + ch * 16);
    }

    float o[8][4] = {};
    float mrow0 = 0.f, mrow1 = 0.f, lrow0 = 0.f, lrow1 = 0.f;  // lazy shift, init 0
    const int g = lane >> 2, c = lane & 3;
    const int brow0 = warp * 16 + g, brow1 = brow0 + 8;

    for (int t = 0; t < 16; t++) {
        cpwait<1>();
        __syncthreads();

        const uint32_t cur = st0 + (t & 1) * ASTG;
        const uint32_t kH = cur, vH = cur + 8192;
        const char* bsm = dynsm + 16384 + (t & 1) * ASTG + 16384;

        // S = Qh Kh^T over 64 keys
        float sfr[8][4] = {};
#pragma unroll
        for (int kc = 0; kc < 4; kc++) {
            uint32_t kbh[4][4];
#pragma unroll
            for (int pr = 0; pr < 4; pr++) {
                int row = pr * 16 + ((lane >> 4) << 3) + (lane & 7);
                int ch = (kc * 2 + ((lane >> 3) & 1)) ^ (row & 7);
                ldmx4(kbh[pr][0], kbh[pr][1], kbh[pr][2], kbh[pr][3], kH + row * 128 + ch * 16);
            }
#pragma unroll
            for (int nt = 0; nt < 8; nt++)
                mma16816(sfr[nt], qh[kc],
                         kbh[nt >> 1][(nt & 1) * 2], kbh[nt >> 1][(nt & 1) * 2 + 1]);
        }

        // bias (FMA with LOG2E)
#pragma unroll
        for (int nt = 0; nt < 8; nt++) {
            int col = nt * 8 + 2 * c;
            int chunk = col >> 2, within = (col & 3) * 4;
            float2 b01 = *(const float2*)(bsm + brow0 * 256 + ((chunk ^ (brow0 & 15)) << 4) + within);
            float2 b23 = *(const float2*)(bsm + brow1 * 256 + ((chunk ^ (brow1 & 15)) << 4) + within);
            sfr[nt][0] = fmaf(b01.x, LOG2E, sfr[nt][0]);
            sfr[nt][1] = fmaf(b01.y, LOG2E, sfr[nt][1]);
            sfr[nt][2] = fmaf(b23.x, LOG2E, sfr[nt][2]);
            sfr[nt][3] = fmaf(b23.y, LOG2E, sfr[nt][3]);
        }

        // P = ex2(S - m_old) in fp16 (lazy shift); row sums via ones-MMA; O += P V
        float sacc[4] = {0.f, 0.f, 0.f, 0.f};
#pragma unroll
        for (int kc = 0; kc < 4; kc++) {
            uint32_t pa[4];
            pa[0] = ex2h2(pack_half2(sfr[2 * kc][0] - mrow0,     sfr[2 * kc][1] - mrow0));
            pa[1] = ex2h2(pack_half2(sfr[2 * kc][2] - mrow1,     sfr[2 * kc][3] - mrow1));
            pa[2] = ex2h2(pack_half2(sfr[2 * kc + 1][0] - mrow0, sfr[2 * kc + 1][1] - mrow0));
            pa[3] = ex2h2(pack_half2(sfr[2 * kc + 1][2] - mrow1, sfr[2 * kc + 1][3] - mrow1));
            mma16816(sacc, pa, ONES2, ONES2);
#pragma unroll
            for (int pr = 0; pr < 4; pr++) {
                int row = kc * 16 + ((lane >> 3) & 1) * 8 + (lane & 7);
                int ch = (2 * pr + (lane >> 4)) ^ (row & 7);
                uint32_t vh0, vh1, vh2, vh3;
                ldmx4t(vh0, vh1, vh2, vh3, vH + row * 128 + ch * 16);
                mma16816(o[2 * pr],     pa, vh0, vh1);
                mma16816(o[2 * pr + 1], pa, vh2, vh3);
            }
        }
        lrow0 += sacc[0];
        lrow1 += sacc[2];

        // update shift for next stage (off the S->exp->PV critical path)
        if (t + 1 < 16) {
            float mx0 = -1e30f, mx1 = -1e30f;
#pragma unroll
            for (int nt = 0; nt < 8; nt++) {
                mx0 = fmaxf(mx0, fmaxf(sfr[nt][0], sfr[nt][1]));
                mx1 = fmaxf(mx1, fmaxf(sfr[nt][2], sfr[nt][3]));
            }
            mx0 = fmaxf(mx0, __shfl_xor_sync(0xffffffffu, mx0, 1));
            mx0 = fmaxf(mx0, __shfl_xor_sync(0xffffffffu, mx0, 2));
            mx1 = fmaxf(mx1, __shfl_xor_sync(0xffffffffu, mx1, 1));
            mx1 = fmaxf(mx1, __shfl_xor_sync(0xffffffffu, mx1, 2));
            float mn0 = fmaxf(mrow0, mx0), mn1 = fmaxf(mrow1, mx1);
            float al0 = (mn0 == mrow0) ? 1.0f : ex2f(mrow0 - mn0);
            float al1 = (mn1 == mrow1) ? 1.0f : ex2f(mrow1 - mn1);
            mrow0 = mn0; mrow1 = mn1;
            if ((al0 != 1.0f) || (al1 != 1.0f)) {
                lrow0 *= al0; lrow1 *= al1;
#pragma unroll
                for (int nt = 0; nt < 8; nt++) {
                    o[nt][0] *= al0; o[nt][1] *= al0;
                    o[nt][2] *= al1; o[nt][3] *= al1;
                }
            }
        }

        __syncthreads();
        if (t + 2 < 16)
            attn_load_stage(st0 + (t & 1) * ASTG, base, bb, (t + 2) * 64, n0, tid);
        cpcommit();
    }

    // epilogue: normalize, round to fp16, store [N, B, E]
    const float inv0 = 1.f / lrow0, inv1 = 1.f / lrow1;
    const int bg = bh / NH, hh = bh - bg * NH;
    const int r0g = n0 + warp * 16 + g;
#pragma unroll
    for (int nt = 0; nt < 8; nt++) {
        int d = nt * 8 + 2 * c;
        size_t i0 = ((size_t)r0g * NG + bg) * EDIM + hh * HD + d;
        size_t i1 = ((size_t)(r0g + 8) * NG + bg) * EDIM + hh * HD + d;
        *(uint32_t*)&g_ah[i0] = pack_half2(o[nt][0] * inv0, o[nt][1] * inv0);
        *(uint32_t*)&g_ah[i1] = pack_half2(o[nt][2] * inv1, o[nt][3] * inv1);
    }
}

// ---------------------------------------------------------------------------
extern "C" void kernel_launch(void* const* d_in, const int* in_sizes, int n_in,
                              void* d_out, int out_size) {
    const float* query     = (const float*)d_in[0];
    const float* attn_bias = (const float*)d_in[1];
    const void*  mask      = d_in[2];
    const float* W_in      = (const float*)d_in[3];
    const float* b_in      = (const float*)d_in[4];
    const float* W_out     = (const float*)d_in[5];
    const float* b_out     = (const float*)d_in[6];
    float* out = (float*)d_out;

    prep_kernel<<<PREP_BLOCKS, 256>>>(
        (const float4*)query, (const float4*)W_in, (const float4*)W_out,
        (const uint8_t*)mask);

    const int gsm = 3 * GSTG;  // 96 KB
    cudaFuncSetAttribute((const void*)qkv_gemm_kernel,
                         cudaFuncAttributeMaxDynamicSharedMemorySize, gsm);
    qkv_gemm_kernel<<<dim3(32, 18), 256, gsm>>>(b_in);

    const int asmb = 16384 + 2 * ASTG;  // 114688 -> 2 CTAs/SM
    cudaFuncSetAttribute((const void*)attn_kernel,
                         cudaFuncAttributeMaxDynamicSharedMemorySize, asmb);
    attn_kernel<<<dim3(8, BHD), 256, asmb>>>(attn_bias);

    const int osm = 4 * OSTG;  // 96 KB
    cudaFuncSetAttribute((const void*)out_gemm_kernel,
                         cudaFuncAttributeMaxDynamicSharedMemorySize, osm);
    out_gemm_kernel<<<dim3(64, 6), 256, osm>>>(b_out, mask, out);
}

// round 14
// speedup vs baseline: 1.0840x; 1.0840x over previous
#include <cuda_runtime.h>
#include <cuda_fp16.h>
#include <cstdint>

#define NG    4
#define NH    12
#define BHD   48
#define NNODE 1024
#define EDIM  768
#define HD    64
#define QSCALE 0.125f
#define LOG2E  1.4426950408889634f
#define MROWS 4096

// ---------------- scratch (no cudaMalloc allowed) ----------------
__device__ __half g_qxh[MROWS * EDIM];       // query rounded fp16
__device__ __half g_wih[3 * EDIM * EDIM];    // W_in rounded
__device__ __half g_woh[EDIM * EDIM];        // W_out rounded
__device__ __half g_qh[BHD * NNODE * HD];    // q rounded (scaled by QSCALE*LOG2E)
__device__ __half g_kh[BHD * NNODE * HD];    // k rounded
__device__ __half g_vh[BHD * NNODE * HD];    // v rounded
__device__ __half g_ah[MROWS * EDIM];        // attn out rounded
__device__ int    g_mask_kind;

// ---------------- helpers ----------------
__device__ __forceinline__ uint32_t smem_u32(const void* p) {
    return (uint32_t)__cvta_generic_to_shared(p);
}
__device__ __forceinline__ void cp16(uint32_t dst, const void* src) {
    asm volatile("cp.async.cg.shared.global [%0],[%1],16;\n" :: "r"(dst), "l"(src) : "memory");
}
__device__ __forceinline__ void cpcommit() {
    asm volatile("cp.async.commit_group;\n" ::: "memory");
}
template<int N> __device__ __forceinline__ void cpwait() {
    asm volatile("cp.async.wait_group %0;\n" :: "n"(N) : "memory");
}
__device__ __forceinline__ void ldmx4(uint32_t& r0, uint32_t& r1, uint32_t& r2, uint32_t& r3, uint32_t a) {
    asm volatile("ldmatrix.sync.aligned.m8n8.x4.shared.b16 {%0,%1,%2,%3},[%4];\n"
                 : "=r"(r0), "=r"(r1), "=r"(r2), "=r"(r3) : "r"(a));
}
__device__ __forceinline__ void ldmx4t(uint32_t& r0, uint32_t& r1, uint32_t& r2, uint32_t& r3, uint32_t a) {
    asm volatile("ldmatrix.sync.aligned.m8n8.x4.trans.shared.b16 {%0,%1,%2,%3},[%4];\n"
                 : "=r"(r0), "=r"(r1), "=r"(r2), "=r"(r3) : "r"(a));
}
__device__ __forceinline__ void mma16816(float* c, const uint32_t* a, uint32_t b0, uint32_t b1) {
    asm volatile("mma.sync.aligned.m16n8k16.row.col.f32.f16.f16.f32 "
                 "{%0,%1,%2,%3},{%4,%5,%6,%7},{%8,%9},{%0,%1,%2,%3};\n"
                 : "+f"(c[0]), "+f"(c[1]), "+f"(c[2]), "+f"(c[3])
                 : "r"(a[0]), "r"(a[1]), "r"(a[2]), "r"(a[3]), "r"(b0), "r"(b1));
}
__device__ __forceinline__ uint32_t pack_half2(float x, float y) {
    __half2 h = __floats2half2_rn(x, y);
    return *reinterpret_cast<uint32_t*>(&h);
}
__device__ __forceinline__ float ex2f(float x) {
    float y; asm("ex2.approx.ftz.f32 %0,%1;" : "=f"(y) : "f"(x)); return y;
}
__device__ __forceinline__ uint32_t ex2h2(uint32_t x) {
    uint32_t y; asm("ex2.approx.f16x2 %0,%1;" : "=r"(y) : "r"(x)); return y;
}

// ---------------- fused prep: round q/W_in/W_out; last block also probes mask
#define NQ4  (MROWS * EDIM / 4)
#define NWI4 (3 * EDIM * EDIM / 4)
#define NWO4 (EDIM * EDIM / 4)
#define PREP_BLOCKS ((NQ4 + NWI4 + NWO4 + 255) / 256)
__global__ void prep_kernel(const float4* __restrict__ q,
                            const float4* __restrict__ wi,
                            const float4* __restrict__ wo,
                            const uint8_t* __restrict__ mask) {
    int i = blockIdx.x * blockDim.x + threadIdx.x;
    if (i < NQ4) {
        float4 f = q[i];
        ((uint2*)g_qxh)[i] = make_uint2(pack_half2(f.x, f.y), pack_half2(f.z, f.w));
    } else if (i < NQ4 + NWI4) {
        int j = i - NQ4;
        float4 f = wi[j];
        ((uint2*)g_wih)[j] = make_uint2(pack_half2(f.x, f.y), pack_half2(f.z, f.w));
    } else if (i < NQ4 + NWI4 + NWO4) {
        int j = i - NQ4 - NWI4;
        float4 f = wo[j];
        ((uint2*)g_woh)[j] = make_uint2(pack_half2(f.x, f.y), pack_half2(f.z, f.w));
    }
    if (blockIdx.x == gridDim.x - 1) {
        __shared__ int or_b0, or_b123;
        if (threadIdx.x == 0) { or_b0 = 0; or_b123 = 0; }
        __syncthreads();
        int a0 = 0, a123 = 0;
        for (int w = threadIdx.x; w < 1024; w += blockDim.x) {
            a0   |= mask[4 * w];
            a123 |= mask[4 * w + 1] | mask[4 * w + 2] | mask[4 * w + 3];
        }
        if (a0)   atomicOr(&or_b0, 1);
        if (a123) atomicOr(&or_b123, 1);
        __syncthreads();
        if (threadIdx.x == 0) {
            if (or_b0 == 0)        g_mask_kind = 2;
            else if (or_b123 == 0) g_mask_kind = 1;
            else                   g_mask_kind = 0;
        }
    }
}

// ============================================================================
// qkv GEMM: BM=128, BN=128, BK=64, 256 threads (8 warps 2x4), warp 64x32.
// 3-stage cp.async ring, one barrier per k-iter (12 iters).
// ============================================================================
#define GSTG 32768   // A 16384 + B 16384

__device__ __forceinline__ void gemm_load_stage(
    uint32_t sbase, const __half* A, const __half* B,
    int m0, int n0, int k0, int tid)
{
    uint32_t aH = sbase, bH = sbase + 16384;
#pragma unroll
    for (int it = 0; it < 4; it++) {
        int s = tid + it * 256;
        int row = s >> 3, ch = s & 7;
        uint32_t off = (uint32_t)(row * 128 + ((ch ^ (row & 7)) * 16));
        cp16(aH + off, A + (size_t)(m0 + row) * EDIM + k0 + ch * 8);
        cp16(bH + off, B + (size_t)(n0 + row) * EDIM + k0 + ch * 8);
    }
}

__device__ __forceinline__ void gemm_compute_stage(
    uint32_t sbase, int lane, int wm, int wn, float acc[4][4][4])
{
    uint32_t aH = sbase, bH = sbase + 16384;
#pragma unroll
    for (int kc = 0; kc < 4; kc++) {
        uint32_t ah[4][4], bh[2][4];
#pragma unroll
        for (int mt = 0; mt < 4; mt++) {
            int row = wm + mt * 16 + (lane & 15);
            int ch = (kc * 2 + (lane >> 4)) ^ (row & 7);
            ldmx4(ah[mt][0], ah[mt][1], ah[mt][2], ah[mt][3], aH + row * 128 + ch * 16);
        }
#pragma unroll
        for (int pr = 0; pr < 2; pr++) {
            int row = wn + pr * 16 + ((lane >> 4) << 3) + (lane & 7);
            int ch = (kc * 2 + ((lane >> 3) & 1)) ^ (row & 7);
            ldmx4(bh[pr][0], bh[pr][1], bh[pr][2], bh[pr][3], bH + row * 128 + ch * 16);
        }
#pragma unroll
        for (int mt = 0; mt < 4; mt++)
#pragma unroll
            for (int nt = 0; nt < 4; nt++)
                mma16816(acc[mt][nt], ah[mt],
                         bh[nt >> 1][(nt & 1) * 2], bh[nt >> 1][(nt & 1) * 2 + 1]);
    }
}

__global__ __launch_bounds__(256, 2) void qkv_gemm_kernel(const float* __restrict__ bias)
{
    extern __shared__ __align__(16) char dynsm[];
    const int tid = threadIdx.x, lane = tid & 31, warp = tid >> 5;
    const int wm = (warp >> 2) * 64, wn = (warp & 3) * 32;
    const int m0 = blockIdx.x * 128, n0 = blockIdx.y * 128;
    const uint32_t sb = smem_u32(dynsm);
    gemm_load_stage(sb,        g_qxh, g_wih, m0, n0, 0,  tid);
    cpcommit();
    gemm_load_stage(sb + GSTG, g_qxh, g_wih, m0, n0, 64, tid);
    cpcommit();
    float acc[4][4][4] = {};
    for (int kt = 0; kt < 12; kt++) {
        cpwait<1>();
        __syncthreads();
        gemm_compute_stage(sb + (kt % 3) * GSTG, lane, wm, wn, acc);
        if (kt + 2 < 12)
            gemm_load_stage(sb + ((kt + 2) % 3) * GSTG, g_qxh, g_wih,
                            m0, n0, (kt + 2) * 64, tid);
        cpcommit();
    }

    const int g = lane >> 2, c = lane & 3;
    const int sec = n0 / EDIM;
    const int colbase = n0 - sec * EDIM;
    const float sc = (sec == 0) ? QSCALE * LOG2E : 1.0f;
    __half* dst = (sec == 0) ? g_qh : (sec == 1 ? g_kh : g_vh);
#pragma unroll
    for (int mt = 0; mt < 4; mt++)
#pragma unroll
        for (int nt = 0; nt < 4; nt++) {
            int dloc = wn + nt * 8 + 2 * c;
            int e = colbase + dloc;
            int hh = e >> 6, d = e & 63;
            float bv0 = bias[n0 + dloc], bv1 = bias[n0 + dloc + 1];
#pragma unroll
            for (int rr = 0; rr < 2; rr++) {
                int row = m0 + wm + mt * 16 + g + rr * 8;
                int node = row >> 2, bg = row & 3;
                float v0 = (acc[mt][nt][rr * 2 + 0] + bv0) * sc;
                float v1 = (acc[mt][nt][rr * 2 + 1] + bv1) * sc;
                size_t idx = (((size_t)(bg * NH + hh) * NNODE + node) * HD + d);
                *(uint32_t*)&dst[idx] = pack_half2(v0, v1);
            }
        }
}

// ============================================================================
// out GEMM: BM=64, BN=128, BK=64, 256 threads (8 warps 2x4), warp 32x32.
// 3-stage ring (round-12 config, measured 21.5us).
// ============================================================================
#define OSTG 24576   // A 8192 + B 16384

__device__ __forceinline__ void ogemm_load_stage(
    uint32_t sbase, int m0, int n0, int k0, int tid)
{
    uint32_t aH = sbase, bH = sbase + 8192;
#pragma unroll
    for (int it = 0; it < 2; it++) {
        int s = tid + it * 256;
        int row = s >> 3, ch = s & 7;
        uint32_t off = (uint32_t)(row * 128 + ((ch ^ (row & 7)) * 16));
        cp16(aH + off, g_ah + (size_t)(m0 + row) * EDIM + k0 + ch * 8);
    }
#pragma unroll
    for (int it = 0; it < 4; it++) {
        int s = tid + it * 256;
        int row = s >> 3, ch = s & 7;
        uint32_t off = (uint32_t)(row * 128 + ((ch ^ (row & 7)) * 16));
        cp16(bH + off, g_woh + (size_t)(n0 + row) * EDIM + k0 + ch * 8);
    }
}

__device__ __forceinline__ void ogemm_compute_stage(
    uint32_t sbase, int lane, int wm, int wn, float acc[2][4][4])
{
    uint32_t aH = sbase, bH = sbase + 8192;
#pragma unroll
    for (int kc = 0; kc < 4; kc++) {
        uint32_t ah[2][4], bh[2][4];
#pragma unroll
        for (int mt = 0; mt < 2; mt++) {
            int row = wm + mt * 16 + (lane & 15);
            int ch = (kc * 2 + (lane >> 4)) ^ (row & 7);
            ldmx4(ah[mt][0], ah[mt][1], ah[mt][2], ah[mt][3], aH + row * 128 + ch * 16);
        }
#pragma unroll
        for (int pr = 0; pr < 2; pr++) {
            int row = wn + pr * 16 + ((lane >> 4) << 3) + (lane & 7);
            int ch = (kc * 2 + ((lane >> 3) & 1)) ^ (row & 7);
            ldmx4(bh[pr][0], bh[pr][1], bh[pr][2], bh[pr][3], bH + row * 128 + ch * 16);
        }
#pragma unroll
        for (int mt = 0; mt < 2; mt++)
#pragma unroll
            for (int nt = 0; nt < 4; nt++)
                mma16816(acc[mt][nt], ah[mt],
                         bh[nt >> 1][(nt & 1) * 2], bh[nt >> 1][(nt & 1) * 2 + 1]);
    }
}

__global__ __launch_bounds__(256, 2) void out_gemm_kernel(
    const float* __restrict__ bias, const void* __restrict__ maskp,
    float* __restrict__ out)
{
    extern __shared__ __align__(16) char dynsm[];
    const int tid = threadIdx.x, lane = tid & 31, warp = tid >> 5;
    const int wm = (warp >> 2) * 32, wn = (warp & 3) * 32;
    const int m0 = blockIdx.x * 64, n0 = blockIdx.y * 128;
    const uint32_t sb = smem_u32(dynsm);
    ogemm_load_stage(sb,        m0, n0, 0,  tid);
    cpcommit();
    ogemm_load_stage(sb + OSTG, m0, n0, 64, tid);
    cpcommit();
    float acc[2][4][4] = {};
    for (int kt = 0; kt < 12; kt++) {
        cpwait<1>();
        __syncthreads();
        ogemm_compute_stage(sb + (kt % 3) * OSTG, lane, wm, wn, acc);
        if (kt + 2 < 12)
            ogemm_load_stage(sb + ((kt + 2) % 3) * OSTG, m0, n0, (kt + 2) * 64, tid);
        cpcommit();
    }

    const int g = lane >> 2, c = lane & 3;
    const int mkind = g_mask_kind;
#pragma unroll
    for (int mt = 0; mt < 2; mt++)
#pragma unroll
        for (int rr = 0; rr < 2; rr++) {
            int row = m0 + wm + mt * 16 + g + rr * 8;
            int node = row >> 2, bg = row & 3;
            int midx = bg * NNODE + node;
            bool keep;
            if (mkind == 1)      keep = ((const int*)maskp)[midx] != 0;
            else if (mkind == 2) keep = ((const float*)maskp)[midx] != 0.0f;
            else                 keep = ((const uint8_t*)maskp)[midx] != 0;
#pragma unroll
            for (int nt = 0; nt < 4; nt++) {
                int col = n0 + wn + nt * 8 + 2 * c;
                float v0 = keep ? (acc[mt][nt][rr * 2 + 0] + bias[col])     : 0.0f;
                float v1 = keep ? (acc[mt][nt][rr * 2 + 1] + bias[col + 1]) : 0.0f;
                *(float2*)&out[(size_t)row * EDIM + col] = make_float2(v0, v1);
            }
        }
}

// ============================================================================
// Kernel 2: flash attention, 64 q-rows x 1 head per CTA, 4 warps (128 thr),
// 3 CTAs/SM. Grid (16, 48) = 768 CTAs over 444 slots -> makespan 2 small waves.
// 16 key-stages of 64 keys; 2-stage cp.async ring (KV + fp32 bias, XOR smem).
// Lazy (one-stage-delayed) max; P via ex2.f16x2; row sums via ones-MMA.
// Per-warp math identical to the 128-row version.
// ============================================================================
#define ASTG 32768    // Kh 8192 + Vh 8192 + bias 16384 (64 rows)
#define ONES2 0x3C003C00u

__device__ __forceinline__ void attn_load_stage(
    uint32_t sbase, size_t kvbase, const float* bb, int m0, int n0, int tid)
{
    uint32_t kH = sbase, vH = sbase + 8192, bS = sbase + 16384;
#pragma unroll
    for (int it = 0; it < 4; it++) {
        int s = tid + it * 128;
        int row = s >> 3, ch = s & 7;
        uint32_t off = (uint32_t)(row * 128 + ((ch ^ (row & 7)) * 16));
        size_t gi = kvbase + (size_t)(m0 + row) * HD + ch * 8;
        cp16(kH + off, g_kh + gi);
        cp16(vH + off, g_vh + gi);
    }
#pragma unroll
    for (int it = 0; it < 8; it++) {
        int s = tid + it * 128;
        int row = s >> 4, ch = s & 15;
        cp16(bS + (uint32_t)(row * 256 + ((ch ^ (row & 15)) << 4)),
             bb + (size_t)(n0 + row) * NNODE + m0 + ch * 4);
    }
}

__global__ __launch_bounds__(128, 3) void attn_kernel(const float* __restrict__ bias)
{
    extern __shared__ __align__(16) char dynsm[];
    const int tid = threadIdx.x, lane = tid & 31, warp = tid >> 5;
    const int bh = blockIdx.y, n0 = blockIdx.x * 64;
    const size_t base = (size_t)bh * NNODE * HD;
    const float* bb = bias + ((size_t)bh << 20);

    const uint32_t qH = smem_u32(dynsm);
    const uint32_t st0 = qH + 8192;

    // prologue: Q (own group), then stages 0,1
#pragma unroll
    for (int it = 0; it < 4; it++) {
        int s = tid + it * 128;
        int row = s >> 3, ch = s & 7;
        uint32_t off = (uint32_t)(row * 128 + ((ch ^ (row & 7)) * 16));
        cp16(qH + off, g_qh + base + (size_t)(n0 + row) * HD + ch * 8);
    }
    cpcommit();
    attn_load_stage(st0, base, bb, 0, n0, tid);
    cpcommit();
    attn_load_stage(st0 + ASTG, base, bb, 64, n0, tid);
    cpcommit();

    cpwait<2>();
    __syncthreads();
    uint32_t qh[4][4];
#pragma unroll
    for (int kc = 0; kc < 4; kc++) {
        int row = warp * 16 + (lane & 15);
        int ch = (kc * 2 + (lane >> 4)) ^ (row & 7);
        ldmx4(qh[kc][0], qh[kc][1], qh[kc][2], qh[kc][3], qH + row * 128 + ch * 16);
    }

    float o[8][4] = {};
    float mrow0 = 0.f, mrow1 = 0.f, lrow0 = 0.f, lrow1 = 0.f;  // lazy shift
    const int g = lane >> 2, c = lane & 3;
    const int brow0 = warp * 16 + g, brow1 = brow0 + 8;

    for (int t = 0; t < 16; t++) {
        cpwait<1>();
        __syncthreads();

        const uint32_t cur = st0 + (t & 1) * ASTG;
        const uint32_t kH = cur, vH = cur + 8192;
        const char* bsm = dynsm + 8192 + (t & 1) * ASTG + 16384;

        // S = Qh Kh^T over 64 keys
        float sfr[8][4] = {};
#pragma unroll
        for (int kc = 0; kc < 4; kc++) {
            uint32_t kbh[4][4];
#pragma unroll
            for (int pr = 0; pr < 4; pr++) {
                int row = pr * 16 + ((lane >> 4) << 3) + (lane & 7);
                int ch = (kc * 2 + ((lane >> 3) & 1)) ^ (row & 7);
                ldmx4(kbh[pr][0], kbh[pr][1], kbh[pr][2], kbh[pr][3], kH + row * 128 + ch * 16);
            }
#pragma unroll
            for (int nt = 0; nt < 8; nt++)
                mma16816(sfr[nt], qh[kc],
                         kbh[nt >> 1][(nt & 1) * 2], kbh[nt >> 1][(nt & 1) * 2 + 1]);
        }

        // bias (FMA with LOG2E)
#pragma unroll
        for (int nt = 0; nt < 8; nt++) {
            int col = nt * 8 + 2 * c;
            int chunk = col >> 2, within = (col & 3) * 4;
            float2 b01 = *(const float2*)(bsm + brow0 * 256 + ((chunk ^ (brow0 & 15)) << 4) + within);
            float2 b23 = *(const float2*)(bsm + brow1 * 256 + ((chunk ^ (brow1 & 15)) << 4) + within);
            sfr[nt][0] = fmaf(b01.x, LOG2E, sfr[nt][0]);
            sfr[nt][1] = fmaf(b01.y, LOG2E, sfr[nt][1]);
            sfr[nt][2] = fmaf(b23.x, LOG2E, sfr[nt][2]);
            sfr[nt][3] = fmaf(b23.y, LOG2E, sfr[nt][3]);
        }

        // P = ex2(S - m_old) in fp16 (lazy shift); row sums via ones-MMA; O += P V
        float sacc[4] = {0.f, 0.f, 0.f, 0.f};
#pragma unroll
        for (int kc = 0; kc < 4; kc++) {
            uint32_t pa[4];
            pa[0] = ex2h2(pack_half2(sfr[2 * kc][0] - mrow0,     sfr[2 * kc][1] - mrow0));
            pa[1] = ex2h2(pack_half2(sfr[2 * kc][2] - mrow1,     sfr[2 * kc][3] - mrow1));
            pa[2] = ex2h2(pack_half2(sfr[2 * kc + 1][0] - mrow0, sfr[2 * kc + 1][1] - mrow0));
            pa[3] = ex2h2(pack_half2(sfr[2 * kc + 1][2] - mrow1, sfr[2 * kc + 1][3] - mrow1));
            mma16816(sacc, pa, ONES2, ONES2);
#pragma unroll
            for (int pr = 0; pr < 4; pr++) {
                int row = kc * 16 + ((lane >> 3) & 1) * 8 + (lane & 7);
                int ch = (2 * pr + (lane >> 4)) ^ (row & 7);
                uint32_t vh0, vh1, vh2, vh3;
                ldmx4t(vh0, vh1, vh2, vh3, vH + row * 128 + ch * 16);
                mma16816(o[2 * pr],     pa, vh0, vh1);
                mma16816(o[2 * pr + 1], pa, vh2, vh3);
            }
        }
        lrow0 += sacc[0];
        lrow1 += sacc[2];

        // update shift for next stage (off the S->exp->PV critical path)
        if (t + 1 < 16) {
            float mx0 = -1e30f, mx1 = -1e30f;
#pragma unroll
            for (int nt = 0; nt < 8; nt++) {
                mx0 = fmaxf(mx0, fmaxf(sfr[nt][0], sfr[nt][1]));
                mx1 = fmaxf(mx1, fmaxf(sfr[nt][2], sfr[nt][3]));
            }
            mx0 = fmaxf(mx0, __shfl_xor_sync(0xffffffffu, mx0, 1));
            mx0 = fmaxf(mx0, __shfl_xor_sync(0xffffffffu, mx0, 2));
            mx1 = fmaxf(mx1, __shfl_xor_sync(0xffffffffu, mx1, 1));
            mx1 = fmaxf(mx1, __shfl_xor_sync(0xffffffffu, mx1, 2));
            float mn0 = fmaxf(mrow0, mx0), mn1 = fmaxf(mrow1, mx1);
            float al0 = (mn0 == mrow0) ? 1.0f : ex2f(mrow0 - mn0);
            float al1 = (mn1 == mrow1) ? 1.0f : ex2f(mrow1 - mn1);
            mrow0 = mn0; mrow1 = mn1;
            if ((al0 != 1.0f) || (al1 != 1.0f)) {
                lrow0 *= al0; lrow1 *= al1;
#pragma unroll
                for (int nt = 0; nt < 8; nt++) {
                    o[nt][0] *= al0; o[nt][1] *= al0;
                    o[nt][2] *= al1; o[nt][3] *= al1;
                }
            }
        }

        __syncthreads();
        if (t + 2 < 16)
            attn_load_stage(st0 + (t & 1) * ASTG, base, bb, (t + 2) * 64, n0, tid);
        cpcommit();
    }

    // epilogue: normalize, round to fp16, store [N, B, E]
    const float inv0 = 1.f / lrow0, inv1 = 1.f / lrow1;
    const int bg = bh / NH, hh = bh - bg * NH;
    const int r0g = n0 + warp * 16 + g;
#pragma unroll
    for (int nt = 0; nt < 8; nt++) {
        int d = nt * 8 + 2 * c;
        size_t i0 = ((size_t)r0g * NG + bg) * EDIM + hh * HD + d;
        size_t i1 = ((size_t)(r0g + 8) * NG + bg) * EDIM + hh * HD + d;
        *(uint32_t*)&g_ah[i0] = pack_half2(o[nt][0] * inv0, o[nt][1] * inv0);
        *(uint32_t*)&g_ah[i1] = pack_half2(o[nt][2] * inv1, o[nt][3] * inv1);
    }
}

// ---------------------------------------------------------------------------
extern "C" void kernel_launch(void* const* d_in, const int* in_sizes, int n_in,
                              void* d_out, int out_size) {
    const float* query     = (const float*)d_in[0];
    const float* attn_bias = (const float*)d_in[1];
    const void*  mask      = d_in[2];
    const float* W_in      = (const float*)d_in[3];
    const float* b_in      = (const float*)d_in[4];
    const float* W_out     = (const float*)d_in[5];
    const float* b_out     = (const float*)d_in[6];
    float* out = (float*)d_out;

    prep_kernel<<<PREP_BLOCKS, 256>>>(
        (const float4*)query, (const float4*)W_in, (const float4*)W_out,
        (const uint8_t*)mask);

    const int gsm = 3 * GSTG;  // 96 KB
    cudaFuncSetAttribute((const void*)qkv_gemm_kernel,
                         cudaFuncAttributeMaxDynamicSharedMemorySize, gsm);
    qkv_gemm_kernel<<<dim3(32, 18), 256, gsm>>>(b_in);

    const int asmb = 8192 + 2 * ASTG;  // 73728 -> 3 CTAs/SM
    cudaFuncSetAttribute((const void*)attn_kernel,
                         cudaFuncAttributeMaxDynamicSharedMemorySize, asmb);
    attn_kernel<<<dim3(16, BHD), 128, asmb>>>(attn_bias);

    const int osm = 3 * OSTG;  // 72 KB
    cudaFuncSetAttribute((const void*)out_gemm_kernel,
                         cudaFuncAttributeMaxDynamicSharedMemorySize, osm);
    out_gemm_kernel<<<dim3(64, 6), 256, osm>>>(b_out, mask, out);
}

// round 15
// speedup vs baseline: 1.0865x; 1.0023x over previous
#include <cuda_runtime.h>
#include <cuda_fp16.h>
#include <cstdint>

#define NG    4
#define NH    12
#define BHD   48
#define NNODE 1024
#define EDIM  768
#define HD    64
#define QSCALE 0.125f
#define LOG2E  1.4426950408889634f
#define MROWS 4096

// ---------------- scratch (no cudaMalloc allowed) ----------------
__device__ __half g_qxh[MROWS * EDIM];       // query rounded fp16
__device__ __half g_wih[3 * EDIM * EDIM];    // W_in rounded
__device__ __half g_woh[EDIM * EDIM];        // W_out rounded
__device__ __half g_qh[BHD * NNODE * HD];    // q rounded (scaled by QSCALE*LOG2E)
__device__ __half g_kh[BHD * NNODE * HD];    // k rounded
__device__ __half g_vh[BHD * NNODE * HD];    // v rounded
__device__ __half g_ah[MROWS * EDIM];        // attn out rounded
__device__ int    g_mask_kind;

// ---------------- helpers ----------------
__device__ __forceinline__ uint32_t smem_u32(const void* p) {
    return (uint32_t)__cvta_generic_to_shared(p);
}
__device__ __forceinline__ void cp16(uint32_t dst, const void* src) {
    asm volatile("cp.async.cg.shared.global [%0],[%1],16;\n" :: "r"(dst), "l"(src) : "memory");
}
__device__ __forceinline__ void cpcommit() {
    asm volatile("cp.async.commit_group;\n" ::: "memory");
}
template<int N> __device__ __forceinline__ void cpwait() {
    asm volatile("cp.async.wait_group %0;\n" :: "n"(N) : "memory");
}
__device__ __forceinline__ void ldmx4(uint32_t& r0, uint32_t& r1, uint32_t& r2, uint32_t& r3, uint32_t a) {
    asm volatile("ldmatrix.sync.aligned.m8n8.x4.shared.b16 {%0,%1,%2,%3},[%4];\n"
                 : "=r"(r0), "=r"(r1), "=r"(r2), "=r"(r3) : "r"(a));
}
__device__ __forceinline__ void ldmx4t(uint32_t& r0, uint32_t& r1, uint32_t& r2, uint32_t& r3, uint32_t a) {
    asm volatile("ldmatrix.sync.aligned.m8n8.x4.trans.shared.b16 {%0,%1,%2,%3},[%4];\n"
                 : "=r"(r0), "=r"(r1), "=r"(r2), "=r"(r3) : "r"(a));
}
__device__ __forceinline__ void mma16816(float* c, const uint32_t* a, uint32_t b0, uint32_t b1) {
    asm volatile("mma.sync.aligned.m16n8k16.row.col.f32.f16.f16.f32 "
                 "{%0,%1,%2,%3},{%4,%5,%6,%7},{%8,%9},{%0,%1,%2,%3};\n"
                 : "+f"(c[0]), "+f"(c[1]), "+f"(c[2]), "+f"(c[3])
                 : "r"(a[0]), "r"(a[1]), "r"(a[2]), "r"(a[3]), "r"(b0), "r"(b1));
}
__device__ __forceinline__ uint32_t pack_half2(float x, float y) {
    __half2 h = __floats2half2_rn(x, y);
    return *reinterpret_cast<uint32_t*>(&h);
}
__device__ __forceinline__ float ex2f(float x) {
    float y; asm("ex2.approx.ftz.f32 %0,%1;" : "=f"(y) : "f"(x)); return y;
}
__device__ __forceinline__ uint32_t ex2h2(uint32_t x) {
    uint32_t y; asm("ex2.approx.f16x2 %0,%1;" : "=r"(y) : "r"(x)); return y;
}

// ---------------- fused prep: round q/W_in/W_out; last block also probes mask
#define NQ4  (MROWS * EDIM / 4)
#define NWI4 (3 * EDIM * EDIM / 4)
#define NWO4 (EDIM * EDIM / 4)
#define PREP_BLOCKS ((NQ4 + NWI4 + NWO4 + 255) / 256)
__global__ void prep_kernel(const float4* __restrict__ q,
                            const float4* __restrict__ wi,
                            const float4* __restrict__ wo,
                            const uint8_t* __restrict__ mask) {
    int i = blockIdx.x * blockDim.x + threadIdx.x;
    if (i < NQ4) {
        float4 f = q[i];
        ((uint2*)g_qxh)[i] = make_uint2(pack_half2(f.x, f.y), pack_half2(f.z, f.w));
    } else if (i < NQ4 + NWI4) {
        int j = i - NQ4;
        float4 f = wi[j];
        ((uint2*)g_wih)[j] = make_uint2(pack_half2(f.x, f.y), pack_half2(f.z, f.w));
    } else if (i < NQ4 + NWI4 + NWO4) {
        int j = i - NQ4 - NWI4;
        float4 f = wo[j];
        ((uint2*)g_woh)[j] = make_uint2(pack_half2(f.x, f.y), pack_half2(f.z, f.w));
    }
    if (blockIdx.x == gridDim.x - 1) {
        __shared__ int or_b0, or_b123;
        if (threadIdx.x == 0) { or_b0 = 0; or_b123 = 0; }
        __syncthreads();
        int a0 = 0, a123 = 0;
        for (int w = threadIdx.x; w < 1024; w += blockDim.x) {
            a0   |= mask[4 * w];
            a123 |= mask[4 * w + 1] | mask[4 * w + 2] | mask[4 * w + 3];
        }
        if (a0)   atomicOr(&or_b0, 1);
        if (a123) atomicOr(&or_b123, 1);
        __syncthreads();
        if (threadIdx.x == 0) {
            if (or_b0 == 0)        g_mask_kind = 2;
            else if (or_b123 == 0) g_mask_kind = 1;
            else                   g_mask_kind = 0;
        }
    }
}

// ============================================================================
// qkv GEMM: BM=128, BN=128, BK=64, 256 threads (8 warps 2x4), warp 64x32.
// 3-stage cp.async ring; loads for kt+2 issued BEFORE compute(kt).
// ============================================================================
#define GSTG 32768   // A 16384 + B 16384

__device__ __forceinline__ void gemm_load_stage(
    uint32_t sbase, const __half* A, const __half* B,
    int m0, int n0, int k0, int tid)
{
    uint32_t aH = sbase, bH = sbase + 16384;
#pragma unroll
    for (int it = 0; it < 4; it++) {
        int s = tid + it * 256;
        int row = s >> 3, ch = s & 7;
        uint32_t off = (uint32_t)(row * 128 + ((ch ^ (row & 7)) * 16));
        cp16(aH + off, A + (size_t)(m0 + row) * EDIM + k0 + ch * 8);
        cp16(bH + off, B + (size_t)(n0 + row) * EDIM + k0 + ch * 8);
    }
}

__device__ __forceinline__ void gemm_compute_stage(
    uint32_t sbase, int lane, int wm, int wn, float acc[4][4][4])
{
    uint32_t aH = sbase, bH = sbase + 16384;
#pragma unroll
    for (int kc = 0; kc < 4; kc++) {
        uint32_t ah[4][4], bh[2][4];
#pragma unroll
        for (int mt = 0; mt < 4; mt++) {
            int row = wm + mt * 16 + (lane & 15);
            int ch = (kc * 2 + (lane >> 4)) ^ (row & 7);
            ldmx4(ah[mt][0], ah[mt][1], ah[mt][2], ah[mt][3], aH + row * 128 + ch * 16);
        }
#pragma unroll
        for (int pr = 0; pr < 2; pr++) {
            int row = wn + pr * 16 + ((lane >> 4) << 3) + (lane & 7);
            int ch = (kc * 2 + ((lane >> 3) & 1)) ^ (row & 7);
            ldmx4(bh[pr][0], bh[pr][1], bh[pr][2], bh[pr][3], bH + row * 128 + ch * 16);
        }
#pragma unroll
        for (int mt = 0; mt < 4; mt++)
#pragma unroll
            for (int nt = 0; nt < 4; nt++)
                mma16816(acc[mt][nt], ah[mt],
                         bh[nt >> 1][(nt & 1) * 2], bh[nt >> 1][(nt & 1) * 2 + 1]);
    }
}

__global__ __launch_bounds__(256, 2) void qkv_gemm_kernel(const float* __restrict__ bias)
{
    extern __shared__ __align__(16) char dynsm[];
    const int tid = threadIdx.x, lane = tid & 31, warp = tid >> 5;
    const int wm = (warp >> 2) * 64, wn = (warp & 3) * 32;
    const int m0 = blockIdx.x * 128, n0 = blockIdx.y * 128;
    const uint32_t sb = smem_u32(dynsm);
    gemm_load_stage(sb,        g_qxh, g_wih, m0, n0, 0,  tid);
    cpcommit();
    gemm_load_stage(sb + GSTG, g_qxh, g_wih, m0, n0, 64, tid);
    cpcommit();
    float acc[4][4][4] = {};
    for (int kt = 0; kt < 12; kt++) {
        cpwait<1>();
        __syncthreads();
        if (kt + 2 < 12)
            gemm_load_stage(sb + ((kt + 2) % 3) * GSTG, g_qxh, g_wih,
                            m0, n0, (kt + 2) * 64, tid);
        cpcommit();
        gemm_compute_stage(sb + (kt % 3) * GSTG, lane, wm, wn, acc);
    }

    const int g = lane >> 2, c = lane & 3;
    const int sec = n0 / EDIM;
    const int colbase = n0 - sec * EDIM;
    const float sc = (sec == 0) ? QSCALE * LOG2E : 1.0f;
    __half* dst = (sec == 0) ? g_qh : (sec == 1 ? g_kh : g_vh);
#pragma unroll
    for (int mt = 0; mt < 4; mt++)
#pragma unroll
        for (int nt = 0; nt < 4; nt++) {
            int dloc = wn + nt * 8 + 2 * c;
            int e = colbase + dloc;
            int hh = e >> 6, d = e & 63;
            float bv0 = bias[n0 + dloc], bv1 = bias[n0 + dloc + 1];
#pragma unroll
            for (int rr = 0; rr < 2; rr++) {
                int row = m0 + wm + mt * 16 + g + rr * 8;
                int node = row >> 2, bg = row & 3;
                float v0 = (acc[mt][nt][rr * 2 + 0] + bv0) * sc;
                float v1 = (acc[mt][nt][rr * 2 + 1] + bv1) * sc;
                size_t idx = (((size_t)(bg * NH + hh) * NNODE + node) * HD + d);
                *(uint32_t*)&dst[idx] = pack_half2(v0, v1);
            }
        }
}

// ============================================================================
// out GEMM: BM=64, BN=128, BK=64, 256 threads (8 warps 2x4), warp 32x32.
// 3-stage ring; loads for kt+2 issued BEFORE compute(kt).
// ============================================================================
#define OSTG 24576   // A 8192 + B 16384

__device__ __forceinline__ void ogemm_load_stage(
    uint32_t sbase, int m0, int n0, int k0, int tid)
{
    uint32_t aH = sbase, bH = sbase + 8192;
#pragma unroll
    for (int it = 0; it < 2; it++) {
        int s = tid + it * 256;
        int row = s >> 3, ch = s & 7;
        uint32_t off = (uint32_t)(row * 128 + ((ch ^ (row & 7)) * 16));
        cp16(aH + off, g_ah + (size_t)(m0 + row) * EDIM + k0 + ch * 8);
    }
#pragma unroll
    for (int it = 0; it < 4; it++) {
        int s = tid + it * 256;
        int row = s >> 3, ch = s & 7;
        uint32_t off = (uint32_t)(row * 128 + ((ch ^ (row & 7)) * 16));
        cp16(bH + off, g_woh + (size_t)(n0 + row) * EDIM + k0 + ch * 8);
    }
}

__device__ __forceinline__ void ogemm_compute_stage(
    uint32_t sbase, int lane, int wm, int wn, float acc[2][4][4])
{
    uint32_t aH = sbase, bH = sbase + 8192;
#pragma unroll
    for (int kc = 0; kc < 4; kc++) {
        uint32_t ah[2][4], bh[2][4];
#pragma unroll
        for (int mt = 0; mt < 2; mt++) {
            int row = wm + mt * 16 + (lane & 15);
            int ch = (kc * 2 + (lane >> 4)) ^ (row & 7);
            ldmx4(ah[mt][0], ah[mt][1], ah[mt][2], ah[mt][3], aH + row * 128 + ch * 16);
        }
#pragma unroll
        for (int pr = 0; pr < 2; pr++) {
            int row = wn + pr * 16 + ((lane >> 4) << 3) + (lane & 7);
            int ch = (kc * 2 + ((lane >> 3) & 1)) ^ (row & 7);
            ldmx4(bh[pr][0], bh[pr][1], bh[pr][2], bh[pr][3], bH + row * 128 + ch * 16);
        }
#pragma unroll
        for (int mt = 0; mt < 2; mt++)
#pragma unroll
            for (int nt = 0; nt < 4; nt++)
                mma16816(acc[mt][nt], ah[mt],
                         bh[nt >> 1][(nt & 1) * 2], bh[nt >> 1][(nt & 1) * 2 + 1]);
    }
}

__global__ __launch_bounds__(256, 2) void out_gemm_kernel(
    const float* __restrict__ bias, const void* __restrict__ maskp,
    float* __restrict__ out)
{
    extern __shared__ __align__(16) char dynsm[];
    const int tid = threadIdx.x, lane = tid & 31, warp = tid >> 5;
    const int wm = (warp >> 2) * 32, wn = (warp & 3) * 32;
    const int m0 = blockIdx.x * 64, n0 = blockIdx.y * 128;
    const uint32_t sb = smem_u32(dynsm);
    ogemm_load_stage(sb,        m0, n0, 0,  tid);
    cpcommit();
    ogemm_load_stage(sb + OSTG, m0, n0, 64, tid);
    cpcommit();
    float acc[2][4][4] = {};
    for (int kt = 0; kt < 12; kt++) {
        cpwait<1>();
        __syncthreads();
        if (kt + 2 < 12)
            ogemm_load_stage(sb + ((kt + 2) % 3) * OSTG, m0, n0, (kt + 2) * 64, tid);
        cpcommit();
        ogemm_compute_stage(sb + (kt % 3) * OSTG, lane, wm, wn, acc);
    }

    const int g = lane >> 2, c = lane & 3;
    const int mkind = g_mask_kind;
#pragma unroll
    for (int mt = 0; mt < 2; mt++)
#pragma unroll
        for (int rr = 0; rr < 2; rr++) {
            int row = m0 + wm + mt * 16 + g + rr * 8;
            int node = row >> 2, bg = row & 3;
            int midx = bg * NNODE + node;
            bool keep;
            if (mkind == 1)      keep = ((const int*)maskp)[midx] != 0;
            else if (mkind == 2) keep = ((const float*)maskp)[midx] != 0.0f;
            else                 keep = ((const uint8_t*)maskp)[midx] != 0;
#pragma unroll
            for (int nt = 0; nt < 4; nt++) {
                int col = n0 + wn + nt * 8 + 2 * c;
                float v0 = keep ? (acc[mt][nt][rr * 2 + 0] + bias[col])     : 0.0f;
                float v1 = keep ? (acc[mt][nt][rr * 2 + 1] + bias[col + 1]) : 0.0f;
                *(float2*)&out[(size_t)row * EDIM + col] = make_float2(v0, v1);
            }
        }
}

// ============================================================================
// Kernel 2: flash attention, 64 q-rows x 1 head per CTA, 4 warps (128 thr),
// 3 CTAs/SM (round-14 configuration, measured best).
// ============================================================================
#define ASTG 32768    // Kh 8192 + Vh 8192 + bias 16384 (64 rows)
#define ONES2 0x3C003C00u

__device__ __forceinline__ void attn_load_stage(
    uint32_t sbase, size_t kvbase, const float* bb, int m0, int n0, int tid)
{
    uint32_t kH = sbase, vH = sbase + 8192, bS = sbase + 16384;
#pragma unroll
    for (int it = 0; it < 4; it++) {
        int s = tid + it * 128;
        int row = s >> 3, ch = s & 7;
        uint32_t off = (uint32_t)(row * 128 + ((ch ^ (row & 7)) * 16));
        size_t gi = kvbase + (size_t)(m0 + row) * HD + ch * 8;
        cp16(kH + off, g_kh + gi);
        cp16(vH + off, g_vh + gi);
    }
#pragma unroll
    for (int it = 0; it < 8; it++) {
        int s = tid + it * 128;
        int row = s >> 4, ch = s & 15;
        cp16(bS + (uint32_t)(row * 256 + ((ch ^ (row & 15)) << 4)),
             bb + (size_t)(n0 + row) * NNODE + m0 + ch * 4);
    }
}

__global__ __launch_bounds__(128, 3) void attn_kernel(const float* __restrict__ bias)
{
    extern __shared__ __align__(16) char dynsm[];
    const int tid = threadIdx.x, lane = tid & 31, warp = tid >> 5;
    const int bh = blockIdx.y, n0 = blockIdx.x * 64;
    const size_t base = (size_t)bh * NNODE * HD;
    const float* bb = bias + ((size_t)bh << 20);

    const uint32_t qH = smem_u32(dynsm);
    const uint32_t st0 = qH + 8192;

    // prologue: Q (own group), then stages 0,1
#pragma unroll
    for (int it = 0; it < 4; it++) {
        int s = tid + it * 128;
        int row = s >> 3, ch = s & 7;
        uint32_t off = (uint32_t)(row * 128 + ((ch ^ (row & 7)) * 16));
        cp16(qH + off, g_qh + base + (size_t)(n0 + row) * HD + ch * 8);
    }
    cpcommit();
    attn_load_stage(st0, base, bb, 0, n0, tid);
    cpcommit();
    attn_load_stage(st0 + ASTG, base, bb, 64, n0, tid);
    cpcommit();

    cpwait<2>();
    __syncthreads();
    uint32_t qh[4][4];
#pragma unroll
    for (int kc = 0; kc < 4; kc++) {
        int row = warp * 16 + (lane & 15);
        int ch = (kc * 2 + (lane >> 4)) ^ (row & 7);
        ldmx4(qh[kc][0], qh[kc][1], qh[kc][2], qh[kc][3], qH + row * 128 + ch * 16);
    }

    float o[8][4] = {};
    float mrow0 = 0.f, mrow1 = 0.f, lrow0 = 0.f, lrow1 = 0.f;  // lazy shift
    const int g = lane >> 2, c = lane & 3;
    const int brow0 = warp * 16 + g, brow1 = brow0 + 8;

    for (int t = 0; t < 16; t++) {
        cpwait<1>();
        __syncthreads();

        const uint32_t cur = st0 + (t & 1) * ASTG;
        const uint32_t kH = cur, vH = cur + 8192;
        const char* bsm = dynsm + 8192 + (t & 1) * ASTG + 16384;

        // S = Qh Kh^T over 64 keys
        float sfr[8][4] = {};
#pragma unroll
        for (int kc = 0; kc < 4; kc++) {
            uint32_t kbh[4][4];
#pragma unroll
            for (int pr = 0; pr < 4; pr++) {
                int row = pr * 16 + ((lane >> 4) << 3) + (lane & 7);
                int ch = (kc * 2 + ((lane >> 3) & 1)) ^ (row & 7);
                ldmx4(kbh[pr][0], kbh[pr][1], kbh[pr][2], kbh[pr][3], kH + row * 128 + ch * 16);
            }
#pragma unroll
            for (int nt = 0; nt < 8; nt++)
                mma16816(sfr[nt], qh[kc],
                         kbh[nt >> 1][(nt & 1) * 2], kbh[nt >> 1][(nt & 1) * 2 + 1]);
        }

        // bias (FMA with LOG2E)
#pragma unroll
        for (int nt = 0; nt < 8; nt++) {
            int col = nt * 8 + 2 * c;
            int chunk = col >> 2, within = (col & 3) * 4;
            float2 b01 = *(const float2*)(bsm + brow0 * 256 + ((chunk ^ (brow0 & 15)) << 4) + within);
            float2 b23 = *(const float2*)(bsm + brow1 * 256 + ((chunk ^ (brow1 & 15)) << 4) + within);
            sfr[nt][0] = fmaf(b01.x, LOG2E, sfr[nt][0]);
            sfr[nt][1] = fmaf(b01.y, LOG2E, sfr[nt][1]);
            sfr[nt][2] = fmaf(b23.x, LOG2E, sfr[nt][2]);
            sfr[nt][3] = fmaf(b23.y, LOG2E, sfr[nt][3]);
        }

        // P = ex2(S - m_old) in fp16 (lazy shift); row sums via ones-MMA; O += P V
        float sacc[4] = {0.f, 0.f, 0.f, 0.f};
#pragma unroll
        for (int kc = 0; kc < 4; kc++) {
            uint32_t pa[4];
            pa[0] = ex2h2(pack_half2(sfr[2 * kc][0] - mrow0,     sfr[2 * kc][1] - mrow0));
            pa[1] = ex2h2(pack_half2(sfr[2 * kc][2] - mrow1,     sfr[2 * kc][3] - mrow1));
            pa[2] = ex2h2(pack_half2(sfr[2 * kc + 1][0] - mrow0, sfr[2 * kc + 1][1] - mrow0));
            pa[3] = ex2h2(pack_half2(sfr[2 * kc + 1][2] - mrow1, sfr[2 * kc + 1][3] - mrow1));
            mma16816(sacc, pa, ONES2, ONES2);
#pragma unroll
            for (int pr = 0; pr < 4; pr++) {
                int row = kc * 16 + ((lane >> 3) & 1) * 8 + (lane & 7);
                int ch = (2 * pr + (lane >> 4)) ^ (row & 7);
                uint32_t vh0, vh1, vh2, vh3;
                ldmx4t(vh0, vh1, vh2, vh3, vH + row * 128 + ch * 16);
                mma16816(o[2 * pr],     pa, vh0, vh1);
                mma16816(o[2 * pr + 1], pa, vh2, vh3);
            }
        }
        lrow0 += sacc[0];
        lrow1 += sacc[2];

        // update shift for next stage (off the S->exp->PV critical path)
        if (t + 1 < 16) {
            float mx0 = -1e30f, mx1 = -1e30f;
#pragma unroll
            for (int nt = 0; nt < 8; nt++) {
                mx0 = fmaxf(mx0, fmaxf(sfr[nt][0], sfr[nt][1]));
                mx1 = fmaxf(mx1, fmaxf(sfr[nt][2], sfr[nt][3]));
            }
            mx0 = fmaxf(mx0, __shfl_xor_sync(0xffffffffu, mx0, 1));
            mx0 = fmaxf(mx0, __shfl_xor_sync(0xffffffffu, mx0, 2));
            mx1 = fmaxf(mx1, __shfl_xor_sync(0xffffffffu, mx1, 1));
            mx1 = fmaxf(mx1, __shfl_xor_sync(0xffffffffu, mx1, 2));
            float mn0 = fmaxf(mrow0, mx0), mn1 = fmaxf(mrow1, mx1);
            float al0 = (mn0 == mrow0) ? 1.0f : ex2f(mrow0 - mn0);
            float al1 = (mn1 == mrow1) ? 1.0f : ex2f(mrow1 - mn1);
            mrow0 = mn0; mrow1 = mn1;
            if ((al0 != 1.0f) || (al1 != 1.0f)) {
                lrow0 *= al0; lrow1 *= al1;
#pragma unroll
                for (int nt = 0; nt < 8; nt++) {
                    o[nt][0] *= al0; o[nt][1] *= al0;
                    o[nt][2] *= al1; o[nt][3] *= al1;
                }
            }
        }

        __syncthreads();
        if (t + 2 < 16)
            attn_load_stage(st0 + (t & 1) * ASTG, base, bb, (t + 2) * 64, n0, tid);
        cpcommit();
    }

    // epilogue: normalize, round to fp16, store [N, B, E]
    const float inv0 = 1.f / lrow0, inv1 = 1.f / lrow1;
    const int bg = bh / NH, hh = bh - bg * NH;
    const int r0g = n0 + warp * 16 + g;
#pragma unroll
    for (int nt = 0; nt < 8; nt++) {
        int d = nt * 8 + 2 * c;
        size_t i0 = ((size_t)r0g * NG + bg) * EDIM + hh * HD + d;
        size_t i1 = ((size_t)(r0g + 8) * NG + bg) * EDIM + hh * HD + d;
        *(uint32_t*)&g_ah[i0] = pack_half2(o[nt][0] * inv0, o[nt][1] * inv0);
        *(uint32_t*)&g_ah[i1] = pack_half2(o[nt][2] * inv1, o[nt][3] * inv1);
    }
}

// ---------------------------------------------------------------------------
extern "C" void kernel_launch(void* const* d_in, const int* in_sizes, int n_in,
                              void* d_out, int out_size) {
    const float* query     = (const float*)d_in[0];
    const float* attn_bias = (const float*)d_in[1];
    const void*  mask      = d_in[2];
    const float* W_in      = (const float*)d_in[3];
    const float* b_in      = (const float*)d_in[4];
    const float* W_out     = (const float*)d_in[5];
    const float* b_out     = (const float*)d_in[6];
    float* out = (float*)d_out;

    prep_kernel<<<PREP_BLOCKS, 256>>>(
        (const float4*)query, (const float4*)W_in, (const float4*)W_out,
        (const uint8_t*)mask);

    const int gsm = 3 * GSTG;  // 96 KB
    cudaFuncSetAttribute((const void*)qkv_gemm_kernel,
                         cudaFuncAttributeMaxDynamicSharedMemorySize, gsm);
    qkv_gemm_kernel<<<dim3(32, 18), 256, gsm>>>(b_in);

    const int asmb = 8192 + 2 * ASTG;  // 73728 -> 3 CTAs/SM
    cudaFuncSetAttribute((const void*)attn_kernel,
                         cudaFuncAttributeMaxDynamicSharedMemorySize, asmb);
    attn_kernel<<<dim3(16, BHD), 128, asmb>>>(attn_bias);

    const int osm = 3 * OSTG;  // 72 KB
    cudaFuncSetAttribute((const void*)out_gemm_kernel,
                         cudaFuncAttributeMaxDynamicSharedMemorySize, osm);
    out_gemm_kernel<<<dim3(64, 6), 256, osm>>>(b_out, mask, out);
}

// round 16
// speedup vs baseline: 1.3252x; 1.2197x over previous
#include <cuda_runtime.h>
#include <cuda_fp16.h>
#include <cstdint>

#define NG    4
#define NH    12
#define BHD   48
#define NNODE 1024
#define EDIM  768
#define HD    64
#define QSCALE 0.125f
#define LOG2E  1.4426950408889634f
#define MROWS 4096

// ---------------- scratch (no cudaMalloc allowed) ----------------
__device__ __half g_qxh[MROWS * EDIM];       // query rounded fp16
__device__ __half g_wih[3 * EDIM * EDIM];    // W_in rounded
__device__ __half g_woh[EDIM * EDIM];        // W_out rounded
__device__ __half g_qh[BHD * NNODE * HD];    // q rounded (scaled by QSCALE*LOG2E)
__device__ __half g_kh[BHD * NNODE * HD];    // k rounded
__device__ __half g_vh[BHD * NNODE * HD];    // v rounded
__device__ __half g_ah[MROWS * EDIM];        // attn out rounded (zero-init; masked rows stay 0)
__device__ int    g_mask_kind;
__device__ int    g_active[NG * NNODE];      // per-graph compacted active node list
__device__ int    g_cnt[NG];                 // active counts

// ---------------- helpers ----------------
__device__ __forceinline__ uint32_t smem_u32(const void* p) {
    return (uint32_t)__cvta_generic_to_shared(p);
}
__device__ __forceinline__ void cp16(uint32_t dst, const void* src) {
    asm volatile("cp.async.cg.shared.global [%0],[%1],16;\n" :: "r"(dst), "l"(src) : "memory");
}
__device__ __forceinline__ void cpcommit() {
    asm volatile("cp.async.commit_group;\n" ::: "memory");
}
template<int N> __device__ __forceinline__ void cpwait() {
    asm volatile("cp.async.wait_group %0;\n" :: "n"(N) : "memory");
}
__device__ __forceinline__ void ldmx4(uint32_t& r0, uint32_t& r1, uint32_t& r2, uint32_t& r3, uint32_t a) {
    asm volatile("ldmatrix.sync.aligned.m8n8.x4.shared.b16 {%0,%1,%2,%3},[%4];\n"
                 : "=r"(r0), "=r"(r1), "=r"(r2), "=r"(r3) : "r"(a));
}
__device__ __forceinline__ void ldmx4t(uint32_t& r0, uint32_t& r1, uint32_t& r2, uint32_t& r3, uint32_t a) {
    asm volatile("ldmatrix.sync.aligned.m8n8.x4.trans.shared.b16 {%0,%1,%2,%3},[%4];\n"
                 : "=r"(r0), "=r"(r1), "=r"(r2), "=r"(r3) : "r"(a));
}
__device__ __forceinline__ void mma16816(float* c, const uint32_t* a, uint32_t b0, uint32_t b1) {
    asm volatile("mma.sync.aligned.m16n8k16.row.col.f32.f16.f16.f32 "
                 "{%0,%1,%2,%3},{%4,%5,%6,%7},{%8,%9},{%0,%1,%2,%3};\n"
                 : "+f"(c[0]), "+f"(c[1]), "+f"(c[2]), "+f"(c[3])
                 : "r"(a[0]), "r"(a[1]), "r"(a[2]), "r"(a[3]), "r"(b0), "r"(b1));
}
__device__ __forceinline__ uint32_t pack_half2(float x, float y) {
    __half2 h = __floats2half2_rn(x, y);
    return *reinterpret_cast<uint32_t*>(&h);
}
__device__ __forceinline__ float ex2f(float x) {
    float y; asm("ex2.approx.ftz.f32 %0,%1;" : "=f"(y) : "f"(x)); return y;
}
__device__ __forceinline__ uint32_t ex2h2(uint32_t x) {
    uint32_t y; asm("ex2.approx.f16x2 %0,%1;" : "=r"(y) : "r"(x)); return y;
}

// ---------------- fused prep ----------------
// blocks [0, PREP_BLOCKS): round q/W_in/W_out; block PREP_BLOCKS-1 probes mask
// blocks [PREP_BLOCKS, PREP_BLOCKS+4): build per-graph active-node lists
#define NQ4  (MROWS * EDIM / 4)
#define NWI4 (3 * EDIM * EDIM / 4)
#define NWO4 (EDIM * EDIM / 4)
#define PREP_BLOCKS ((NQ4 + NWI4 + NWO4 + 255) / 256)
__global__ void prep_kernel(const float4* __restrict__ q,
                            const float4* __restrict__ wi,
                            const float4* __restrict__ wo,
                            const uint8_t* __restrict__ mask) {
    if (blockIdx.x >= PREP_BLOCKS) {
        // ---- compaction block for graph bg ----
        const int bg = blockIdx.x - PREP_BLOCKS;
        const int tid = threadIdx.x;
        __shared__ int cs[256];
        __shared__ int ob0, ob123, mk_sh;
        if (tid == 0) { ob0 = 0; ob123 = 0; }
        __syncthreads();
        int a0 = 0, a123 = 0;
        for (int w = tid; w < 1024; w += 256) {
            a0   |= mask[4 * w];
            a123 |= mask[4 * w + 1] | mask[4 * w + 2] | mask[4 * w + 3];
        }
        if (a0)   atomicOr(&ob0, 1);
        if (a123) atomicOr(&ob123, 1);
        __syncthreads();
        if (tid == 0) mk_sh = (ob0 == 0) ? 2 : ((ob123 == 0) ? 1 : 0);
        __syncthreads();
        const int mk = mk_sh;

        bool mv[4]; int c = 0;
#pragma unroll
        for (int j = 0; j < 4; j++) {
            int gi = bg * NNODE + tid * 4 + j;
            bool b;
            if (mk == 1)      b = ((const int*)mask)[gi] != 0;
            else if (mk == 2) b = ((const float*)mask)[gi] != 0.0f;
            else              b = mask[gi] != 0;
            mv[j] = b; c += b;
        }
        cs[tid] = c; __syncthreads();
        for (int off = 1; off < 256; off <<= 1) {
            int v = (tid >= off) ? cs[tid - off] : 0;
            __syncthreads();
            cs[tid] += v;
            __syncthreads();
        }
        int base = cs[tid] - c;
#pragma unroll
        for (int j = 0; j < 4; j++)
            if (mv[j]) { g_active[bg * NNODE + base] = tid * 4 + j; base++; }
        const int total = cs[255];
        __syncthreads();  // global writes visible within block
        const int lastv = (total > 0) ? g_active[bg * NNODE + total - 1] : 0;
        for (int i = total + tid; i < NNODE; i += 256)
            g_active[bg * NNODE + i] = lastv;
        if (tid == 0) g_cnt[bg] = total;
        return;
    }

    int i = blockIdx.x * blockDim.x + threadIdx.x;
    if (i < NQ4) {
        float4 f = q[i];
        ((uint2*)g_qxh)[i] = make_uint2(pack_half2(f.x, f.y), pack_half2(f.z, f.w));
    } else if (i < NQ4 + NWI4) {
        int j = i - NQ4;
        float4 f = wi[j];
        ((uint2*)g_wih)[j] = make_uint2(pack_half2(f.x, f.y), pack_half2(f.z, f.w));
    } else if (i < NQ4 + NWI4 + NWO4) {
        int j = i - NQ4 - NWI4;
        float4 f = wo[j];
        ((uint2*)g_woh)[j] = make_uint2(pack_half2(f.x, f.y), pack_half2(f.z, f.w));
    }
    if (blockIdx.x == PREP_BLOCKS - 1) {
        __shared__ int or_b0, or_b123;
        if (threadIdx.x == 0) { or_b0 = 0; or_b123 = 0; }
        __syncthreads();
        int a0 = 0, a123 = 0;
        for (int w = threadIdx.x; w < 1024; w += blockDim.x) {
            a0   |= mask[4 * w];
            a123 |= mask[4 * w + 1] | mask[4 * w + 2] | mask[4 * w + 3];
        }
        if (a0)   atomicOr(&or_b0, 1);
        if (a123) atomicOr(&or_b123, 1);
        __syncthreads();
        if (threadIdx.x == 0) {
            if (or_b0 == 0)        g_mask_kind = 2;
            else if (or_b123 == 0) g_mask_kind = 1;
            else                   g_mask_kind = 0;
        }
    }
}

// ============================================================================
// qkv GEMM: BM=128, BN=128, BK=64, 256 threads (8 warps 2x4), warp 64x32.
// ============================================================================
#define GSTG 32768   // A 16384 + B 16384

__device__ __forceinline__ void gemm_load_stage(
    uint32_t sbase, const __half* A, const __half* B,
    int m0, int n0, int k0, int tid)
{
    uint32_t aH = sbase, bH = sbase + 16384;
#pragma unroll
    for (int it = 0; it < 4; it++) {
        int s = tid + it * 256;
        int row = s >> 3, ch = s & 7;
        uint32_t off = (uint32_t)(row * 128 + ((ch ^ (row & 7)) * 16));
        cp16(aH + off, A + (size_t)(m0 + row) * EDIM + k0 + ch * 8);
        cp16(bH + off, B + (size_t)(n0 + row) * EDIM + k0 + ch * 8);
    }
}

__device__ __forceinline__ void gemm_compute_stage(
    uint32_t sbase, int lane, int wm, int wn, float acc[4][4][4])
{
    uint32_t aH = sbase, bH = sbase + 16384;
#pragma unroll
    for (int kc = 0; kc < 4; kc++) {
        uint32_t ah[4][4], bh[2][4];
#pragma unroll
        for (int mt = 0; mt < 4; mt++) {
            int row = wm + mt * 16 + (lane & 15);
            int ch = (kc * 2 + (lane >> 4)) ^ (row & 7);
            ldmx4(ah[mt][0], ah[mt][1], ah[mt][2], ah[mt][3], aH + row * 128 + ch * 16);
        }
#pragma unroll
        for (int pr = 0; pr < 2; pr++) {
            int row = wn + pr * 16 + ((lane >> 4) << 3) + (lane & 7);
            int ch = (kc * 2 + ((lane >> 3) & 1)) ^ (row & 7);
            ldmx4(bh[pr][0], bh[pr][1], bh[pr][2], bh[pr][3], bH + row * 128 + ch * 16);
        }
#pragma unroll
        for (int mt = 0; mt < 4; mt++)
#pragma unroll
            for (int nt = 0; nt < 4; nt++)
                mma16816(acc[mt][nt], ah[mt],
                         bh[nt >> 1][(nt & 1) * 2], bh[nt >> 1][(nt & 1) * 2 + 1]);
    }
}

__global__ __launch_bounds__(256, 2) void qkv_gemm_kernel(const float* __restrict__ bias)
{
    extern __shared__ __align__(16) char dynsm[];
    const int tid = threadIdx.x, lane = tid & 31, warp = tid >> 5;
    const int wm = (warp >> 2) * 64, wn = (warp & 3) * 32;
    const int m0 = blockIdx.x * 128, n0 = blockIdx.y * 128;
    const uint32_t sb = smem_u32(dynsm);
    gemm_load_stage(sb,        g_qxh, g_wih, m0, n0, 0,  tid);
    cpcommit();
    gemm_load_stage(sb + GSTG, g_qxh, g_wih, m0, n0, 64, tid);
    cpcommit();
    float acc[4][4][4] = {};
    for (int kt = 0; kt < 12; kt++) {
        cpwait<1>();
        __syncthreads();
        if (kt + 2 < 12)
            gemm_load_stage(sb + ((kt + 2) % 3) * GSTG, g_qxh, g_wih,
                            m0, n0, (kt + 2) * 64, tid);
        cpcommit();
        gemm_compute_stage(sb + (kt % 3) * GSTG, lane, wm, wn, acc);
    }

    const int g = lane >> 2, c = lane & 3;
    const int sec = n0 / EDIM;
    const int colbase = n0 - sec * EDIM;
    const float sc = (sec == 0) ? QSCALE * LOG2E : 1.0f;
    __half* dst = (sec == 0) ? g_qh : (sec == 1 ? g_kh : g_vh);
#pragma unroll
    for (int mt = 0; mt < 4; mt++)
#pragma unroll
        for (int nt = 0; nt < 4; nt++) {
            int dloc = wn + nt * 8 + 2 * c;
            int e = colbase + dloc;
            int hh = e >> 6, d = e & 63;
            float bv0 = bias[n0 + dloc], bv1 = bias[n0 + dloc + 1];
#pragma unroll
            for (int rr = 0; rr < 2; rr++) {
                int row = m0 + wm + mt * 16 + g + rr * 8;
                int node = row >> 2, bg = row & 3;
                float v0 = (acc[mt][nt][rr * 2 + 0] + bv0) * sc;
                float v1 = (acc[mt][nt][rr * 2 + 1] + bv1) * sc;
                size_t idx = (((size_t)(bg * NH + hh) * NNODE + node) * HD + d);
                *(uint32_t*)&dst[idx] = pack_half2(v0, v1);
            }
        }
}

// ============================================================================
// out GEMM: BM=64, BN=128, BK=64, 256 threads, 3-stage ring (round-15 config).
// ============================================================================
#define OSTG 24576   // A 8192 + B 16384

__device__ __forceinline__ void ogemm_load_stage(
    uint32_t sbase, int m0, int n0, int k0, int tid)
{
    uint32_t aH = sbase, bH = sbase + 8192;
#pragma unroll
    for (int it = 0; it < 2; it++) {
        int s = tid + it * 256;
        int row = s >> 3, ch = s & 7;
        uint32_t off = (uint32_t)(row * 128 + ((ch ^ (row & 7)) * 16));
        cp16(aH + off, g_ah + (size_t)(m0 + row) * EDIM + k0 + ch * 8);
    }
#pragma unroll
    for (int it = 0; it < 4; it++) {
        int s = tid + it * 256;
        int row = s >> 3, ch = s & 7;
        uint32_t off = (uint32_t)(row * 128 + ((ch ^ (row & 7)) * 16));
        cp16(bH + off, g_woh + (size_t)(n0 + row) * EDIM + k0 + ch * 8);
    }
}

__device__ __forceinline__ void ogemm_compute_stage(
    uint32_t sbase, int lane, int wm, int wn, float acc[2][4][4])
{
    uint32_t aH = sbase, bH = sbase + 8192;
#pragma unroll
    for (int kc = 0; kc < 4; kc++) {
        uint32_t ah[2][4], bh[2][4];
#pragma unroll
        for (int mt = 0; mt < 2; mt++) {
            int row = wm + mt * 16 + (lane & 15);
            int ch = (kc * 2 + (lane >> 4)) ^ (row & 7);
            ldmx4(ah[mt][0], ah[mt][1], ah[mt][2], ah[mt][3], aH + row * 128 + ch * 16);
        }
#pragma unroll
        for (int pr = 0; pr < 2; pr++) {
            int row = wn + pr * 16 + ((lane >> 4) << 3) + (lane & 7);
            int ch = (kc * 2 + ((lane >> 3) & 1)) ^ (row & 7);
            ldmx4(bh[pr][0], bh[pr][1], bh[pr][2], bh[pr][3], bH + row * 128 + ch * 16);
        }
#pragma unroll
        for (int mt = 0; mt < 2; mt++)
#pragma unroll
            for (int nt = 0; nt < 4; nt++)
                mma16816(acc[mt][nt], ah[mt],
                         bh[nt >> 1][(nt & 1) * 2], bh[nt >> 1][(nt & 1) * 2 + 1]);
    }
}

__global__ __launch_bounds__(256, 2) void out_gemm_kernel(
    const float* __restrict__ bias, const void* __restrict__ maskp,
    float* __restrict__ out)
{
    extern __shared__ __align__(16) char dynsm[];
    const int tid = threadIdx.x, lane = tid & 31, warp = tid >> 5;
    const int wm = (warp >> 2) * 32, wn = (warp & 3) * 32;
    const int m0 = blockIdx.x * 64, n0 = blockIdx.y * 128;
    const uint32_t sb = smem_u32(dynsm);
    ogemm_load_stage(sb,        m0, n0, 0,  tid);
    cpcommit();
    ogemm_load_stage(sb + OSTG, m0, n0, 64, tid);
    cpcommit();
    float acc[2][4][4] = {};
    for (int kt = 0; kt < 12; kt++) {
        cpwait<1>();
        __syncthreads();
        if (kt + 2 < 12)
            ogemm_load_stage(sb + ((kt + 2) % 3) * OSTG, m0, n0, (kt + 2) * 64, tid);
        cpcommit();
        ogemm_compute_stage(sb + (kt % 3) * OSTG, lane, wm, wn, acc);
    }

    const int g = lane >> 2, c = lane & 3;
    const int mkind = g_mask_kind;
#pragma unroll
    for (int mt = 0; mt < 2; mt++)
#pragma unroll
        for (int rr = 0; rr < 2; rr++) {
            int row = m0 + wm + mt * 16 + g + rr * 8;
            int node = row >> 2, bg = row & 3;
            int midx = bg * NNODE + node;
            bool keep;
            if (mkind == 1)      keep = ((const int*)maskp)[midx] != 0;
            else if (mkind == 2) keep = ((const float*)maskp)[midx] != 0.0f;
            else                 keep = ((const uint8_t*)maskp)[midx] != 0;
#pragma unroll
            for (int nt = 0; nt < 4; nt++) {
                int col = n0 + wn + nt * 8 + 2 * c;
                float v0 = keep ? (acc[mt][nt][rr * 2 + 0] + bias[col])     : 0.0f;
                float v1 = keep ? (acc[mt][nt][rr * 2 + 1] + bias[col + 1]) : 0.0f;
                *(float2*)&out[(size_t)row * EDIM + col] = make_float2(v0, v1);
            }
        }
}

// ============================================================================
// Kernel 2: flash attention over COMPACTED active q-rows.
// CTA = 64 compacted rows x 1 head, 4 warps, 3 CTAs/SM; CTAs past the active
// count exit immediately (~50% of rows are masked-out and never observed).
// 16 key-stages of 64 keys; 2-stage cp.async ring; lazy max; ex2.f16x2 P;
// row sums via ones-MMA. Per-active-row math identical to round 15.
// ============================================================================
#define ASTG 32768    // Kh 8192 + Vh 8192 + bias 16384
#define IDXOFF (8192 + 2 * ASTG)
#define ONES2 0x3C003C00u

__device__ __forceinline__ void attn_load_stage(
    uint32_t sbase, size_t kvbase, const float* bb, int m0,
    const int* sidx, int tid)
{
    uint32_t kH = sbase, vH = sbase + 8192, bS = sbase + 16384;
#pragma unroll
    for (int it = 0; it < 4; it++) {
        int s = tid + it * 128;
        int row = s >> 3, ch = s & 7;
        uint32_t off = (uint32_t)(row * 128 + ((ch ^ (row & 7)) * 16));
        size_t gi = kvbase + (size_t)(m0 + row) * HD + ch * 8;
        cp16(kH + off, g_kh + gi);
        cp16(vH + off, g_vh + gi);
    }
#pragma unroll
    for (int it = 0; it < 8; it++) {
        int s = tid + it * 128;
        int row = s >> 4, ch = s & 15;
        cp16(bS + (uint32_t)(row * 256 + ((ch ^ (row & 15)) << 4)),
             bb + (size_t)sidx[row] * NNODE + m0 + ch * 4);
    }
}

__global__ __launch_bounds__(128, 3) void attn_kernel(const float* __restrict__ bias)
{
    extern __shared__ __align__(16) char dynsm[];
    const int tid = threadIdx.x, lane = tid & 31, warp = tid >> 5;
    const int bh = blockIdx.y, n0 = blockIdx.x * 64;
    const int bgi = bh / NH;
    if (n0 >= g_cnt[bgi]) return;   // whole tile masked out

    const size_t base = (size_t)bh * NNODE * HD;
    const float* bb = bias + ((size_t)bh << 20);

    const uint32_t qH = smem_u32(dynsm);
    const uint32_t st0 = qH + 8192;
    int* sidx = (int*)(dynsm + IDXOFF);

    if (tid < 64) sidx[tid] = g_active[bgi * NNODE + n0 + tid];
    __syncthreads();

    // prologue: Q (own group, gathered rows), then stages 0,1
#pragma unroll
    for (int it = 0; it < 4; it++) {
        int s = tid + it * 128;
        int row = s >> 3, ch = s & 7;
        uint32_t off = (uint32_t)(row * 128 + ((ch ^ (row & 7)) * 16));
        cp16(qH + off, g_qh + base + (size_t)sidx[row] * HD + ch * 8);
    }
    cpcommit();
    attn_load_stage(st0, base, bb, 0, sidx, tid);
    cpcommit();
    attn_load_stage(st0 + ASTG, base, bb, 64, sidx, tid);
    cpcommit();

    cpwait<2>();
    __syncthreads();
    uint32_t qh[4][4];
#pragma unroll
    for (int kc = 0; kc < 4; kc++) {
        int row = warp * 16 + (lane & 15);
        int ch = (kc * 2 + (lane >> 4)) ^ (row & 7);
        ldmx4(qh[kc][0], qh[kc][1], qh[kc][2], qh[kc][3], qH + row * 128 + ch * 16);
    }

    float o[8][4] = {};
    float mrow0 = 0.f, mrow1 = 0.f, lrow0 = 0.f, lrow1 = 0.f;  // lazy shift
    const int g = lane >> 2, c = lane & 3;
    const int brow0 = warp * 16 + g, brow1 = brow0 + 8;

    for (int t = 0; t < 16; t++) {
        cpwait<1>();
        __syncthreads();

        const uint32_t cur = st0 + (t & 1) * ASTG;
        const uint32_t kH = cur, vH = cur + 8192;
        const char* bsm = dynsm + 8192 + (t & 1) * ASTG + 16384;

        // S = Qh Kh^T over 64 keys
        float sfr[8][4] = {};
#pragma unroll
        for (int kc = 0; kc < 4; kc++) {
            uint32_t kbh[4][4];
#pragma unroll
            for (int pr = 0; pr < 4; pr++) {
                int row = pr * 16 + ((lane >> 4) << 3) + (lane & 7);
                int ch = (kc * 2 + ((lane >> 3) & 1)) ^ (row & 7);
                ldmx4(kbh[pr][0], kbh[pr][1], kbh[pr][2], kbh[pr][3], kH + row * 128 + ch * 16);
            }
#pragma unroll
            for (int nt = 0; nt < 8; nt++)
                mma16816(sfr[nt], qh[kc],
                         kbh[nt >> 1][(nt & 1) * 2], kbh[nt >> 1][(nt & 1) * 2 + 1]);
        }

        // bias (FMA with LOG2E)
#pragma unroll
        for (int nt = 0; nt < 8; nt++) {
            int col = nt * 8 + 2 * c;
            int chunk = col >> 2, within = (col & 3) * 4;
            float2 b01 = *(const float2*)(bsm + brow0 * 256 + ((chunk ^ (brow0 & 15)) << 4) + within);
            float2 b23 = *(const float2*)(bsm + brow1 * 256 + ((chunk ^ (brow1 & 15)) << 4) + within);
            sfr[nt][0] = fmaf(b01.x, LOG2E, sfr[nt][0]);
            sfr[nt][1] = fmaf(b01.y, LOG2E, sfr[nt][1]);
            sfr[nt][2] = fmaf(b23.x, LOG2E, sfr[nt][2]);
            sfr[nt][3] = fmaf(b23.y, LOG2E, sfr[nt][3]);
        }

        // P = ex2(S - m_old) in fp16 (lazy shift); row sums via ones-MMA; O += P V
        float sacc[4] = {0.f, 0.f, 0.f, 0.f};
#pragma unroll
        for (int kc = 0; kc < 4; kc++) {
            uint32_t pa[4];
            pa[0] = ex2h2(pack_half2(sfr[2 * kc][0] - mrow0,     sfr[2 * kc][1] - mrow0));
            pa[1] = ex2h2(pack_half2(sfr[2 * kc][2] - mrow1,     sfr[2 * kc][3] - mrow1));
            pa[2] = ex2h2(pack_half2(sfr[2 * kc + 1][0] - mrow0, sfr[2 * kc + 1][1] - mrow0));
            pa[3] = ex2h2(pack_half2(sfr[2 * kc + 1][2] - mrow1, sfr[2 * kc + 1][3] - mrow1));
            mma16816(sacc, pa, ONES2, ONES2);
#pragma unroll
            for (int pr = 0; pr < 4; pr++) {
                int row = kc * 16 + ((lane >> 3) & 1) * 8 + (lane & 7);
                int ch = (2 * pr + (lane >> 4)) ^ (row & 7);
                uint32_t vh0, vh1, vh2, vh3;
                ldmx4t(vh0, vh1, vh2, vh3, vH + row * 128 + ch * 16);
                mma16816(o[2 * pr],     pa, vh0, vh1);
                mma16816(o[2 * pr + 1], pa, vh2, vh3);
            }
        }
        lrow0 += sacc[0];
        lrow1 += sacc[2];

        // update shift for next stage (off the S->exp->PV critical path)
        if (t + 1 < 16) {
            float mx0 = -1e30f, mx1 = -1e30f;
#pragma unroll
            for (int nt = 0; nt < 8; nt++) {
                mx0 = fmaxf(mx0, fmaxf(sfr[nt][0], sfr[nt][1]));
                mx1 = fmaxf(mx1, fmaxf(sfr[nt][2], sfr[nt][3]));
            }
            mx0 = fmaxf(mx0, __shfl_xor_sync(0xffffffffu, mx0, 1));
            mx0 = fmaxf(mx0, __shfl_xor_sync(0xffffffffu, mx0, 2));
            mx1 = fmaxf(mx1, __shfl_xor_sync(0xffffffffu, mx1, 1));
            mx1 = fmaxf(mx1, __shfl_xor_sync(0xffffffffu, mx1, 2));
            float mn0 = fmaxf(mrow0, mx0), mn1 = fmaxf(mrow1, mx1);
            float al0 = (mn0 == mrow0) ? 1.0f : ex2f(mrow0 - mn0);
            float al1 = (mn1 == mrow1) ? 1.0f : ex2f(mrow1 - mn1);
            mrow0 = mn0; mrow1 = mn1;
            if ((al0 != 1.0f) || (al1 != 1.0f)) {
                lrow0 *= al0; lrow1 *= al1;
#pragma unroll
                for (int nt = 0; nt < 8; nt++) {
                    o[nt][0] *= al0; o[nt][1] *= al0;
                    o[nt][2] *= al1; o[nt][3] *= al1;
                }
            }
        }

        __syncthreads();
        if (t + 2 < 16)
            attn_load_stage(st0 + (t & 1) * ASTG, base, bb, (t + 2) * 64, sidx, tid);
        cpcommit();
    }

    // epilogue: normalize, round to fp16, scatter to [N, B, E] via node index
    const float inv0 = 1.f / lrow0, inv1 = 1.f / lrow1;
    const int hh = bh - bgi * NH;
    const int node0 = sidx[warp * 16 + g];
    const int node1 = sidx[warp * 16 + g + 8];
#pragma unroll
    for (int nt = 0; nt < 8; nt++) {
        int d = nt * 8 + 2 * c;
        size_t i0 = ((size_t)node0 * NG + bgi) * EDIM + hh * HD + d;
        size_t i1 = ((size_t)node1 * NG + bgi) * EDIM + hh * HD + d;
        *(uint32_t*)&g_ah[i0] = pack_half2(o[nt][0] * inv0, o[nt][1] * inv0);
        *(uint32_t*)&g_ah[i1] = pack_half2(o[nt][2] * inv1, o[nt][3] * inv1);
    }
}

// ---------------------------------------------------------------------------
extern "C" void kernel_launch(void* const* d_in, const int* in_sizes, int n_in,
                              void* d_out, int out_size) {
    const float* query     = (const float*)d_in[0];
    const float* attn_bias = (const float*)d_in[1];
    const void*  mask      = d_in[2];
    const float* W_in      = (const float*)d_in[3];
    const float* b_in      = (const float*)d_in[4];
    const float* W_out     = (const float*)d_in[5];
    const float* b_out     = (const float*)d_in[6];
    float* out = (float*)d_out;

    prep_kernel<<<PREP_BLOCKS + 4, 256>>>(
        (const float4*)query, (const float4*)W_in, (const float4*)W_out,
        (const uint8_t*)mask);

    const int gsm = 3 * GSTG;  // 96 KB
    cudaFuncSetAttribute((const void*)qkv_gemm_kernel,
                         cudaFuncAttributeMaxDynamicSharedMemorySize, gsm);
    qkv_gemm_kernel<<<dim3(32, 18), 256, gsm>>>(b_in);

    const int asmb = IDXOFF + 256;  // 73984 -> 3 CTAs/SM
    cudaFuncSetAttribute((const void*)attn_kernel,
                         cudaFuncAttributeMaxDynamicSharedMemorySize, asmb);
    attn_kernel<<<dim3(16, BHD), 128, asmb>>>(attn_bias);

    const int osm = 3 * OSTG;  // 72 KB
    cudaFuncSetAttribute((const void*)out_gemm_kernel,
                         cudaFuncAttributeMaxDynamicSharedMemorySize, osm);
    out_gemm_kernel<<<dim3(64, 6), 256, osm>>>(b_out, mask, out);
}